// round 3
// baseline (speedup 1.0000x reference)
#include <cuda_runtime.h>
#include <cstdint>

#define Nn 50000
#define Mm 24
#define FN 92
#define FE 41
#define Ff 64
#define Cc 128

typedef unsigned long long ull;

// ---- scratch (static device globals; no allocation) ----
__device__ float g_bufA[Nn * Ff];            // 12.8 MB
__device__ float g_bufB[Nn * Ff];            // 12.8 MB
__device__ float g_S[(size_t)Nn * Cc];       // 25.6 MB (PERMUTED col layout)
__device__ float g_P[(size_t)Nn * Cc];       // 25.6 MB (PERMUTED col layout)
__device__ float g_Ut[3 * Cc * 48];          // folded edge weights, transposed [l][c'][k], k padded to 48
__device__ float g_dv[3 * Cc];               // folded edge bias (orig col layout)

// ---- f32x2 packed helpers ----
__device__ __forceinline__ ull pack_dup(float x) {
    ull r; asm("mov.b64 %0, {%1, %1};" : "=l"(r) : "f"(x)); return r;
}
__device__ __forceinline__ ull pack2(float x, float y) {
    ull r; asm("mov.b64 %0, {%1, %2};" : "=l"(r) : "f"(x), "f"(y)); return r;
}
__device__ __forceinline__ void unpack2(ull v, float& x, float& y) {
    asm("mov.b64 {%0, %1}, %2;" : "=f"(x), "=f"(y) : "l"(v));
}
__device__ __forceinline__ void fma2(ull& acc, ull a, ull b) {
    asm("fma.rn.f32x2 %0, %1, %2, %0;" : "+l"(acc) : "l"(a), "l"(b));
}

// ---- fast activations (MUFU) ----
__device__ __forceinline__ float ex2_(float x) { float r; asm("ex2.approx.f32 %0, %1;" : "=f"(r) : "f"(x)); return r; }
__device__ __forceinline__ float lg2_(float x) { float r; asm("lg2.approx.f32 %0, %1;" : "=f"(r) : "f"(x)); return r; }
__device__ __forceinline__ float rcp_(float x) { float r; asm("rcp.approx.f32 %0, %1;" : "=f"(r) : "f"(x)); return r; }

__device__ __forceinline__ float sigmoidf_(float x) {
    return rcp_(1.0f + ex2_(-1.4426950408889634f * x));
}
__device__ __forceinline__ float softplusf_(float x) {
    float a = fabsf(x);
    float e = ex2_(-1.4426950408889634f * a);
    return fmaf(lg2_(1.0f + e), 0.6931471805599453f, fmaxf(x, 0.0f));
}

// ---- tf32 helpers ----
__device__ __forceinline__ uint32_t cvt_tf32(float x) {
    uint32_t r; asm("cvt.rna.tf32.f32 %0, %1;" : "=r"(r) : "f"(x)); return r;
}
__device__ __forceinline__ void mma_tf32(float* c,
                                         uint32_t a0, uint32_t a1, uint32_t a2, uint32_t a3,
                                         uint32_t b0, uint32_t b1) {
    asm volatile("mma.sync.aligned.m16n8k8.row.col.f32.tf32.tf32.f32 "
                 "{%0,%1,%2,%3}, {%4,%5,%6,%7}, {%8,%9}, {%0,%1,%2,%3};"
                 : "+f"(c[0]), "+f"(c[1]), "+f"(c[2]), "+f"(c[3])
                 : "r"(a0), "r"(a1), "r"(a2), "r"(a3), "r"(b0), "r"(b1));
}

// ---- kernel 1: node0 = node_fea @ Wn + bn ----
__global__ void __launch_bounds__(256) k_node_in(const float* __restrict__ nf,
                                                 const float* __restrict__ Wn,
                                                 const float* __restrict__ bn) {
    __shared__ float s_nf[8 * FN];
    int nbase = blockIdx.x * 8;
    for (int i = threadIdx.x; i < 8 * FN; i += 256)
        s_nf[i] = nf[(size_t)nbase * FN + i];
    __syncthreads();
    int g = threadIdx.x >> 5, c = threadIdx.x & 31;
    ull acc = pack2(bn[2 * c], bn[2 * c + 1]);
    const float* nr = &s_nf[g * FN];
#pragma unroll 4
    for (int k = 0; k < FN; k++) {
        ull w = *(const ull*)&Wn[k * Ff + 2 * c];
        fma2(acc, pack_dup(nr[k]), w);
    }
    *(ull*)&g_bufA[(size_t)(nbase + g) * Ff + 2 * c] = acc;
}

// ---- kernel 2: fold U, transposed + permuted + K-padded; plus dv ----
// g_Ut[l][c'][k] = sum_q We[k][q] * W_l[128+q][perm(c')],  k<41, else 0
// perm(c') : even c' -> c'/2 (filter col), odd c' -> 64 + c'/2 (core col)
__global__ void __launch_bounds__(64) k_fold(const float* __restrict__ We,
                                             const float* __restrict__ be,
                                             const float* __restrict__ W1,
                                             const float* __restrict__ W2,
                                             const float* __restrict__ W3) {
    int l = blockIdx.x >> 7;
    int cp = blockIdx.x & 127;
    const float* W = (l == 0) ? W1 : ((l == 1) ? W2 : W3);
    int col = (cp & 1) ? (64 + (cp >> 1)) : (cp >> 1);
    int r = threadIdx.x;  // 0..63
    if (r < 48) {
        float u = 0.0f;
        if (r < FE) {
#pragma unroll 8
            for (int k = 0; k < Ff; k++)
                u = fmaf(We[r * Ff + k], W[(size_t)(128 + k) * Cc + col], u);
        }
        g_Ut[(l * Cc + cp) * 48 + r] = u;
    }
    if (r == 48 && (cp & 1) == 0) {
        // compute dv for orig col (cp>>1) and (64 + cp>>1) handled by odd cp block
    }
    if (r == 49) {
        float dv = 0.0f;
#pragma unroll 8
        for (int k = 0; k < Ff; k++)
            dv = fmaf(be[k], W[(size_t)(128 + k) * Cc + col], dv);
        g_dv[l * Cc + col] = dv;
    }
}

// ---- kernel 3: per-layer S/P precompute (math in orig layout, PERMUTED store) ----
__global__ void __launch_bounds__(256) k_SP(int srcSel, const float* __restrict__ W,
                                            const float* __restrict__ b, int l) {
    const float* node = srcSel ? g_bufB : g_bufA;
    __shared__ float s_nT[64 * 16];
    int nbase = blockIdx.x * 16;
    for (int i = threadIdx.x; i < 1024; i += 256) {
        int k = i & 63, nl = i >> 6;
        s_nT[k * 16 + nl] = node[(size_t)(nbase + nl) * 64 + k];
    }
    __syncthreads();
    int c = threadIdx.x & 63, gq = threadIdx.x >> 6;
    float2 bv = ((const float2*)b)[c];
    float2 dv = ((const float2*)(g_dv + l * Cc))[c];
    ull s0 = pack2(bv.x + dv.x, bv.y + dv.y);
    ull s1 = s0, s2 = s0, s3 = s0;
    ull p0 = 0, p1 = 0, p2 = 0, p3 = 0;
#pragma unroll 4
    for (int k = 0; k < 64; k++) {
        ull wS = *(const ull*)&W[(size_t)k * Cc + 2 * c];
        ull wP = *(const ull*)&W[(size_t)(64 + k) * Cc + 2 * c];
        float4 nv = *(const float4*)&s_nT[k * 16 + gq * 4];
        ull b0 = pack_dup(nv.x); fma2(s0, b0, wS); fma2(p0, b0, wP);
        ull b1 = pack_dup(nv.y); fma2(s1, b1, wS); fma2(p1, b1, wP);
        ull b2 = pack_dup(nv.z); fma2(s2, b2, wS); fma2(p2, b2, wP);
        ull b3 = pack_dup(nv.w); fma2(s3, b3, wS); fma2(p3, b3, wP);
    }
    int n0 = nbase + gq * 4;
    // permuted scatter: orig cols (2c,2c+1) -> new positions c0, c0+2
    int c0 = (c < 32) ? (4 * c) : (4 * c - 127);
    float x, y;
    unpack2(s0, x, y); g_S[(size_t)(n0 + 0) * Cc + c0] = x; g_S[(size_t)(n0 + 0) * Cc + c0 + 2] = y;
    unpack2(s1, x, y); g_S[(size_t)(n0 + 1) * Cc + c0] = x; g_S[(size_t)(n0 + 1) * Cc + c0 + 2] = y;
    unpack2(s2, x, y); g_S[(size_t)(n0 + 2) * Cc + c0] = x; g_S[(size_t)(n0 + 2) * Cc + c0 + 2] = y;
    unpack2(s3, x, y); g_S[(size_t)(n0 + 3) * Cc + c0] = x; g_S[(size_t)(n0 + 3) * Cc + c0 + 2] = y;
    unpack2(p0, x, y); g_P[(size_t)(n0 + 0) * Cc + c0] = x; g_P[(size_t)(n0 + 0) * Cc + c0 + 2] = y;
    unpack2(p1, x, y); g_P[(size_t)(n0 + 1) * Cc + c0] = x; g_P[(size_t)(n0 + 1) * Cc + c0 + 2] = y;
    unpack2(p2, x, y); g_P[(size_t)(n0 + 2) * Cc + c0] = x; g_P[(size_t)(n0 + 2) * Cc + c0 + 2] = y;
    unpack2(p3, x, y); g_P[(size_t)(n0 + 3) * Cc + c0] = x; g_P[(size_t)(n0 + 3) * Cc + c0 + 2] = y;
}

// ---- kernel 4: fused conv layer via tf32 mma ----
// Block: 128 threads (4 warps), 4 nodes => 96 edge rows, K=48, Ncols=128.
// Warp w owns col panel [w*32, w*32+32): B panel (48x32) held in registers.
__global__ void __launch_bounds__(128, 4) k_conv(int srcSel, int dstSel,
                                                 const float* __restrict__ ef,
                                                 const int* __restrict__ idx,
                                                 const float* __restrict__ alpha_p,
                                                 float* __restrict__ outp, int l) {
    const float* nodein = srcSel ? g_bufB : g_bufA;
    float* dst = (dstSel == 0) ? g_bufA : ((dstSel == 1) ? g_bufB : outp);

    __shared__ __align__(16) float s_A[96 * 50];   // 19.2 KB, stride 50 (bank-conflict-free frags)
    __shared__ __align__(16) float s_S2[4 * Cc];   // 2 KB
    __shared__ float s_acc[4 * 64];                // 1 KB
    __shared__ int s_idx[96];

    const int tid = threadIdx.x;
    const int w = tid >> 5, lane = tid & 31;
    const int g = lane >> 2, tig = lane & 3;
    const int nbase = blockIdx.x * 4;

    // ---- B preload into registers (48 regs/thread) ----
    const float* Ut = g_Ut + l * Cc * 48;
    uint32_t B[6][4][2];
#pragma unroll
    for (int kt = 0; kt < 6; kt++)
#pragma unroll
        for (int nt = 0; nt < 4; nt++) {
            const float* p = Ut + (w * 32 + nt * 8 + g) * 48 + kt * 8 + tig;
            B[kt][nt][0] = cvt_tf32(p[0]);
            B[kt][nt][1] = cvt_tf32(p[4]);
        }

    // ---- staging ----
    for (int i = tid; i < 256; i += 128) s_acc[i] = 0.0f;
    for (int i = tid; i < 96; i += 128) s_idx[i] = idx[(size_t)nbase * 24 + i];
    for (int i = tid; i < 512; i += 128) s_S2[i] = g_S[(size_t)nbase * Cc + i];
    for (int i = tid; i < 96 * FE; i += 128) {
        int row = i / FE, r = i - row * FE;
        s_A[row * 50 + r] = ef[(size_t)nbase * 24 * FE + i];
    }
    for (int i = tid; i < 96 * 9; i += 128) {
        int row = i / 9, r = FE + (i - row * 9);
        s_A[row * 50 + r] = 0.0f;
    }
    __syncthreads();

#pragma unroll 1
    for (int mt = 0; mt < 6; mt++) {
        float acc[4][4];
#pragma unroll
        for (int nt = 0; nt < 4; nt++)
#pragma unroll
            for (int q = 0; q < 4; q++) acc[nt][q] = 0.0f;

#pragma unroll
        for (int kt = 0; kt < 6; kt++) {
            const float* ap = &s_A[(mt * 16 + g) * 50 + kt * 8 + tig];
            uint32_t a0 = cvt_tf32(ap[0]);
            uint32_t a1 = cvt_tf32(ap[8 * 50]);
            uint32_t a2 = cvt_tf32(ap[4]);
            uint32_t a3 = cvt_tf32(ap[8 * 50 + 4]);
#pragma unroll
            for (int nt = 0; nt < 4; nt++)
                mma_tf32(acc[nt], a0, a1, a2, a3, B[kt][nt][0], B[kt][nt][1]);
        }

        // ---- epilogue for this M-tile ----
        int row0 = mt * 16 + g, row1 = row0 + 8;
        int i0 = s_idx[row0], i1 = s_idx[row1];
        int so0 = (row0 / 24) * Cc, so1 = (row1 / 24) * Cc;
        int ao0 = (row0 / 24) * 64, ao1 = (row1 / 24) * 64;
#pragma unroll
        for (int nt = 0; nt < 4; nt++) {
            int cc = w * 32 + nt * 8 + tig * 2;
            int jj = cc >> 1;
            if (i0 >= 0) {
                float2 Pv = *(const float2*)&g_P[(size_t)i0 * Cc + cc];
                float2 Sv = *(const float2*)&s_S2[so0 + cc];
                float gf = acc[nt][0] + Sv.x + Pv.x;
                float gc = acc[nt][1] + Sv.y + Pv.y;
                atomicAdd(&s_acc[ao0 + jj], sigmoidf_(gf) * softplusf_(gc));
            }
            if (i1 >= 0) {
                float2 Pv = *(const float2*)&g_P[(size_t)i1 * Cc + cc];
                float2 Sv = *(const float2*)&s_S2[so1 + cc];
                float gf = acc[nt][2] + Sv.x + Pv.x;
                float gc = acc[nt][3] + Sv.y + Pv.y;
                atomicAdd(&s_acc[ao1 + jj], sigmoidf_(gf) * softplusf_(gc));
            }
        }
    }
    __syncthreads();

    // ---- final: out = softplus(alpha*node + nbr_sum) ----
    float alpha = alpha_p[0];
    for (int i = tid; i < 256; i += 128) {
        int gn = i >> 6, j = i & 63;
        size_t n = (size_t)nbase + gn;
        float nin = nodein[n * 64 + j];
        dst[n * 64 + j] = softplusf_(fmaf(alpha, nin, s_acc[i]));
    }
}

extern "C" void kernel_launch(void* const* d_in, const int* in_sizes, int n_in,
                              void* d_out, int out_size) {
    const float* nf  = (const float*)d_in[0];
    const float* ef  = (const float*)d_in[1];
    const int*   idx = (const int*)d_in[2];
    const float* Wn  = (const float*)d_in[3];
    const float* bn  = (const float*)d_in[4];
    const float* We  = (const float*)d_in[5];
    const float* be  = (const float*)d_in[6];
    const float* W[3] = {(const float*)d_in[7], (const float*)d_in[10], (const float*)d_in[13]};
    const float* b[3] = {(const float*)d_in[8], (const float*)d_in[11], (const float*)d_in[14]};
    const float* a[3] = {(const float*)d_in[9], (const float*)d_in[12], (const float*)d_in[15]};
    float* out = (float*)d_out;

    k_node_in<<<Nn / 8, 256>>>(nf, Wn, bn);              // -> g_bufA
    k_fold<<<3 * 128, 64>>>(We, be, W[0], W[1], W[2]);   // -> g_Ut, g_dv

    // layer 1: A -> B
    k_SP<<<Nn / 16, 256>>>(0, W[0], b[0], 0);
    k_conv<<<Nn / 4, 128>>>(0, 1, ef, idx, a[0], out, 0);
    // layer 2: B -> A
    k_SP<<<Nn / 16, 256>>>(1, W[1], b[1], 1);
    k_conv<<<Nn / 4, 128>>>(1, 0, ef, idx, a[1], out, 1);
    // layer 3: A -> d_out
    k_SP<<<Nn / 16, 256>>>(0, W[2], b[2], 2);
    k_conv<<<Nn / 4, 128>>>(0, 2, ef, idx, a[2], out, 2);
}

// round 4
// speedup vs baseline: 1.4733x; 1.4733x over previous
#include <cuda_runtime.h>
#include <cstdint>

#define Nn 50000
#define Mm 24
#define FN 92
#define FE 41
#define Ff 64
#define Cc 128

typedef unsigned long long ull;

// ---- scratch (static device globals; no allocation) ----
__device__ float g_bufA[Nn * Ff];             // 12.8 MB
__device__ float g_bufB[Nn * Ff];             // 12.8 MB
__device__ float g_S[(size_t)Nn * Cc];        // 25.6 MB (perm2 row layout)
__device__ float g_P[(size_t)Nn * Cc];        // 25.6 MB (perm2 row layout)
__device__ uint32_t g_Ua[3 * 8 * 6 * 4 * 32]; // pre-fragmented tf32 A operands
__device__ float g_dv[3 * Cc];                // folded edge bias (orig col layout)

// ---- f32x2 packed helpers ----
__device__ __forceinline__ ull pack_dup(float x) {
    ull r; asm("mov.b64 %0, {%1, %1};" : "=l"(r) : "f"(x)); return r;
}
__device__ __forceinline__ ull pack2(float x, float y) {
    ull r; asm("mov.b64 %0, {%1, %2};" : "=l"(r) : "f"(x), "f"(y)); return r;
}
__device__ __forceinline__ void fma2(ull& acc, ull a, ull b) {
    asm("fma.rn.f32x2 %0, %1, %2, %0;" : "+l"(acc) : "l"(a), "l"(b));
}

// ---- fast activations (MUFU) ----
__device__ __forceinline__ float ex2_(float x) { float r; asm("ex2.approx.f32 %0, %1;" : "=f"(r) : "f"(x)); return r; }
__device__ __forceinline__ float lg2_(float x) { float r; asm("lg2.approx.f32 %0, %1;" : "=f"(r) : "f"(x)); return r; }
__device__ __forceinline__ float rcp_(float x) { float r; asm("rcp.approx.f32 %0, %1;" : "=f"(r) : "f"(x)); return r; }

__device__ __forceinline__ float sigmoidf_(float x) {
    return rcp_(1.0f + ex2_(-1.4426950408889634f * x));
}
__device__ __forceinline__ float softplusf_(float x) {
    float a = fabsf(x);
    float e = ex2_(-1.4426950408889634f * a);
    return fmaf(lg2_(1.0f + e), 0.6931471805599453f, fmaxf(x, 0.0f));
}

// ---- tf32 helpers ----
__device__ __forceinline__ uint32_t cvt_tf32(float x) {
    uint32_t r; asm("cvt.rna.tf32.f32 %0, %1;" : "=r"(r) : "f"(x)); return r;
}
__device__ __forceinline__ void mma_tf32(float* c,
                                         uint32_t a0, uint32_t a1, uint32_t a2, uint32_t a3,
                                         uint32_t b0, uint32_t b1) {
    asm volatile("mma.sync.aligned.m16n8k8.row.col.f32.tf32.tf32.f32 "
                 "{%0,%1,%2,%3}, {%4,%5,%6,%7}, {%8,%9}, {%0,%1,%2,%3};"
                 : "+f"(c[0]), "+f"(c[1]), "+f"(c[2]), "+f"(c[3])
                 : "r"(a0), "r"(a1), "r"(a2), "r"(a3), "r"(b0), "r"(b1));
}

// ---- kernel 1: node0 = node_fea @ Wn + bn ----
__global__ void __launch_bounds__(256) k_node_in(const float* __restrict__ nf,
                                                 const float* __restrict__ Wn,
                                                 const float* __restrict__ bn) {
    __shared__ float s_nf[8 * FN];
    int nbase = blockIdx.x * 8;
    for (int i = threadIdx.x; i < 8 * FN; i += 256)
        s_nf[i] = nf[(size_t)nbase * FN + i];
    __syncthreads();
    int g = threadIdx.x >> 5, c = threadIdx.x & 31;
    ull acc = pack2(bn[2 * c], bn[2 * c + 1]);
    const float* nr = &s_nf[g * FN];
#pragma unroll 4
    for (int k = 0; k < FN; k++) {
        ull w = *(const ull*)&Wn[k * Ff + 2 * c];
        fma2(acc, pack_dup(nr[k]), w);
    }
    *(ull*)&g_bufA[(size_t)(nbase + g) * Ff + 2 * c] = acc;
}

// ---- kernel 2: fold U into pre-arranged tf32 A fragments + dv ----
// A(mrow, k) = U[k][orig(mrow)], U = We @ W_l[128:192,:]
// perm2: mrow = gr*16 + r;  r<8 -> orig col gr*8+r (filter),  r>=8 -> 64+gr*8+(r-8) (core)
// Fragment layout for warp gr: Af[kt][q] at lane = (mrow%16&7)*4 + (k%8&3),
//   q = (r>=8 ? 1:0) + ((k%8)>=4 ? 2:0)
__global__ void __launch_bounds__(256) k_fold(const float* __restrict__ We,
                                              const float* __restrict__ be,
                                              const float* __restrict__ W1,
                                              const float* __restrict__ W2,
                                              const float* __restrict__ W3) {
    int l = blockIdx.x >> 3, gr = blockIdx.x & 7;
    const float* W = (l == 0) ? W1 : ((l == 1) ? W2 : W3);
    for (int i = threadIdx.x; i < 16 * 48; i += 256) {
        int r = i / 48, k = i - r * 48;
        int c = (r < 8) ? (gr * 8 + r) : (64 + gr * 8 + (r - 8));
        float u = 0.0f;
        if (k < FE) {
#pragma unroll 8
            for (int q = 0; q < Ff; q++)
                u = fmaf(We[k * Ff + q], W[(size_t)(128 + q) * Cc + c], u);
        }
        int kt = k >> 3, kin = k & 7;
        int q = ((r >= 8) ? 1 : 0) + ((kin >= 4) ? 2 : 0);
        int ln = (r & 7) * 4 + (kin & 3);
        g_Ua[(((l * 8 + gr) * 6 + kt) * 4 + q) * 32 + ln] = cvt_tf32(u);
    }
    if (threadIdx.x < 16) {
        int c = gr * 16 + threadIdx.x;
        float dv = 0.0f;
#pragma unroll 8
        for (int q = 0; q < Ff; q++)
            dv = fmaf(be[q], W[(size_t)(128 + q) * Cc + c], dv);
        g_dv[l * Cc + c] = dv;
    }
}

// ---- kernel 3: per-layer S/P precompute (orig-layout math, perm2 store) ----
__global__ void __launch_bounds__(256) k_SP(int srcSel, const float* __restrict__ W,
                                            const float* __restrict__ b, int l) {
    const float* node = srcSel ? g_bufB : g_bufA;
    __shared__ float s_nT[64 * 16];
    int nbase = blockIdx.x * 16;
    for (int i = threadIdx.x; i < 1024; i += 256) {
        int k = i & 63, nl = i >> 6;
        s_nT[k * 16 + nl] = node[(size_t)(nbase + nl) * 64 + k];
    }
    __syncthreads();
    int c = threadIdx.x & 63, gq = threadIdx.x >> 6;
    float2 bv = ((const float2*)b)[c];
    float2 dv = ((const float2*)(g_dv + l * Cc))[c];
    ull s0 = pack2(bv.x + dv.x, bv.y + dv.y);
    ull s1 = s0, s2 = s0, s3 = s0;
    ull p0 = 0, p1 = 0, p2 = 0, p3 = 0;
#pragma unroll 4
    for (int k = 0; k < 64; k++) {
        ull wS = *(const ull*)&W[(size_t)k * Cc + 2 * c];
        ull wP = *(const ull*)&W[(size_t)(64 + k) * Cc + 2 * c];
        float4 nv = *(const float4*)&s_nT[k * 16 + gq * 4];
        ull b0 = pack_dup(nv.x); fma2(s0, b0, wS); fma2(p0, b0, wP);
        ull b1 = pack_dup(nv.y); fma2(s1, b1, wS); fma2(p1, b1, wP);
        ull b2 = pack_dup(nv.z); fma2(s2, b2, wS); fma2(p2, b2, wP);
        ull b3 = pack_dup(nv.w); fma2(s3, b3, wS); fma2(p3, b3, wP);
    }
    int n0 = nbase + gq * 4;
    // perm2 position of orig col pair (2c, 2c+1) — pair stays adjacent
    int pos = (c < 32) ? ((c >> 2) * 16 + ((2 * c) & 7))
                       : (((c - 32) >> 2) * 16 + 8 + ((2 * c) & 7));
    *(ull*)&g_S[(size_t)(n0 + 0) * Cc + pos] = s0;
    *(ull*)&g_S[(size_t)(n0 + 1) * Cc + pos] = s1;
    *(ull*)&g_S[(size_t)(n0 + 2) * Cc + pos] = s2;
    *(ull*)&g_S[(size_t)(n0 + 3) * Cc + pos] = s3;
    *(ull*)&g_P[(size_t)(n0 + 0) * Cc + pos] = p0;
    *(ull*)&g_P[(size_t)(n0 + 1) * Cc + pos] = p1;
    *(ull*)&g_P[(size_t)(n0 + 2) * Cc + pos] = p2;
    *(ull*)&g_P[(size_t)(n0 + 3) * Cc + pos] = p3;
}

// ---- kernel 4: fused conv layer, transposed tf32 mma ----
// Block: 256 threads (8 warps), 16 nodes. Warp w = feature group (rows w*16..w*16+15).
// Per node: C[128 feat x 24 edges] = A(U, in regs) x B(ef, smem), 3 n8 tiles x 6 k8 steps.
__global__ void __launch_bounds__(256, 3) k_conv(int srcSel, int dstSel,
                                                 const float* __restrict__ ef,
                                                 const int* __restrict__ idx,
                                                 const float* __restrict__ alpha_p,
                                                 float* __restrict__ outp, int l) {
    const float* nodein = srcSel ? g_bufB : g_bufA;
    float* dst = (dstSel == 0) ? g_bufA : ((dstSel == 1) ? g_bufB : outp);

    __shared__ uint32_t s_ef[24 * 52];              // tf32 ef tile, stride 52
    __shared__ __align__(16) float s_P[24 * 132];   // gathered P rows, stride 132
    __shared__ int s_idx[24];

    const int tid = threadIdx.x;
    const int w = tid >> 5, lane = tid & 31;
    const int lr = lane >> 2, lc = lane & 3;        // frag row / frag col quads
    const int nbase = blockIdx.x * 16;

    // A fragments: 24 coalesced 128B loads, once per block
    uint32_t Af[6][4];
    const uint32_t* Ua = g_Ua + (size_t)(l * 8 + w) * 6 * 128;
#pragma unroll
    for (int kt = 0; kt < 6; kt++)
#pragma unroll
        for (int q = 0; q < 4; q++)
            Af[kt][q] = Ua[kt * 128 + q * 32 + lane];

    const float alpha = __ldg(alpha_p);

    for (int ni = 0; ni < 16; ni++) {
        const int n = nbase + ni;

        // ---- stage P rows (warp w handles edges w*3..w*3+2) ----
#pragma unroll
        for (int r = 0; r < 3; r++) {
            int m = w * 3 + r;
            int ii = __ldg(&idx[n * 24 + m]);
            if (lane == 0) s_idx[m] = ii;
            int iv = (ii < 0) ? 0 : ii;
            float4 v = *(const float4*)&g_P[(size_t)iv * Cc + lane * 4];
            *(float4*)&s_P[m * 132 + lane * 4] = v;
        }
        // ---- stage ef tile (K padded 41 -> 48, tf32-converted) ----
        for (int i = tid; i < 24 * 48; i += 256) {
            int m = i / 48, k = i - m * 48;
            float v = (k < FE) ? ef[(size_t)(n * 24 + m) * FE + k] : 0.0f;
            s_ef[m * 52 + k] = cvt_tf32(v);
        }
        __syncthreads();

        // ---- mma: 3 independent accumulator chains ----
        float c0[4] = {0, 0, 0, 0}, c1[4] = {0, 0, 0, 0}, c2[4] = {0, 0, 0, 0};
#pragma unroll
        for (int kt = 0; kt < 6; kt++) {
            int kb = kt * 8 + lc;
            uint32_t b00 = s_ef[(0 * 8 + lr) * 52 + kb];
            uint32_t b01 = s_ef[(0 * 8 + lr) * 52 + kb + 4];
            uint32_t b10 = s_ef[(1 * 8 + lr) * 52 + kb];
            uint32_t b11 = s_ef[(1 * 8 + lr) * 52 + kb + 4];
            uint32_t b20 = s_ef[(2 * 8 + lr) * 52 + kb];
            uint32_t b21 = s_ef[(2 * 8 + lr) * 52 + kb + 4];
            mma_tf32(c0, Af[kt][0], Af[kt][1], Af[kt][2], Af[kt][3], b00, b01);
            mma_tf32(c1, Af[kt][0], Af[kt][1], Af[kt][2], Af[kt][3], b10, b11);
            mma_tf32(c2, Af[kt][0], Af[kt][1], Af[kt][2], Af[kt][3], b20, b21);
        }

        // ---- epilogue: lane-local (filter, core) pairs, no cross-lane work ----
        float Sf = g_S[(size_t)n * Cc + w * 16 + lr];
        float Sc = g_S[(size_t)n * Cc + w * 16 + 8 + lr];
        float acc = 0.0f;
        float* cp[3] = {c0, c1, c2};
#pragma unroll
        for (int nt = 0; nt < 3; nt++) {
            int e0 = nt * 8 + 2 * lc, e1 = e0 + 1;
            float Pf0 = s_P[e0 * 132 + w * 16 + lr];
            float Pc0 = s_P[e0 * 132 + w * 16 + 8 + lr];
            float Pf1 = s_P[e1 * 132 + w * 16 + lr];
            float Pc1 = s_P[e1 * 132 + w * 16 + 8 + lr];
            if (s_idx[e0] >= 0)
                acc += sigmoidf_(cp[nt][0] + Sf + Pf0) * softplusf_(cp[nt][2] + Sc + Pc0);
            if (s_idx[e1] >= 0)
                acc += sigmoidf_(cp[nt][1] + Sf + Pf1) * softplusf_(cp[nt][3] + Sc + Pc1);
        }
        acc += __shfl_xor_sync(0xffffffffu, acc, 1);
        acc += __shfl_xor_sync(0xffffffffu, acc, 2);

        if (lc == 0) {
            int j = w * 8 + lr;
            float nin = nodein[(size_t)n * Ff + j];
            dst[(size_t)n * Ff + j] = softplusf_(fmaf(alpha, nin, acc));
        }
        __syncthreads();
    }
}

extern "C" void kernel_launch(void* const* d_in, const int* in_sizes, int n_in,
                              void* d_out, int out_size) {
    const float* nf  = (const float*)d_in[0];
    const float* ef  = (const float*)d_in[1];
    const int*   idx = (const int*)d_in[2];
    const float* Wn  = (const float*)d_in[3];
    const float* bn  = (const float*)d_in[4];
    const float* We  = (const float*)d_in[5];
    const float* be  = (const float*)d_in[6];
    const float* W[3] = {(const float*)d_in[7], (const float*)d_in[10], (const float*)d_in[13]};
    const float* b[3] = {(const float*)d_in[8], (const float*)d_in[11], (const float*)d_in[14]};
    const float* a[3] = {(const float*)d_in[9], (const float*)d_in[12], (const float*)d_in[15]};
    float* out = (float*)d_out;

    k_node_in<<<Nn / 8, 256>>>(nf, Wn, bn);              // -> g_bufA
    k_fold<<<24, 256>>>(We, be, W[0], W[1], W[2]);       // -> g_Ua, g_dv

    // layer 1: A -> B
    k_SP<<<Nn / 16, 256>>>(0, W[0], b[0], 0);
    k_conv<<<Nn / 16, 256>>>(0, 1, ef, idx, a[0], out, 0);
    // layer 2: B -> A
    k_SP<<<Nn / 16, 256>>>(1, W[1], b[1], 1);
    k_conv<<<Nn / 16, 256>>>(1, 0, ef, idx, a[1], out, 1);
    // layer 3: A -> d_out
    k_SP<<<Nn / 16, 256>>>(0, W[2], b[2], 2);
    k_conv<<<Nn / 16, 256>>>(0, 2, ef, idx, a[2], out, 2);
}

// round 5
// speedup vs baseline: 2.5737x; 1.7468x over previous
#include <cuda_runtime.h>
#include <cstdint>

#define Nn 50000
#define Mm 24
#define FN 92
#define FE 41
#define Ff 64
#define Cc 128

typedef unsigned long long ull;

// ---- scratch (static device globals; no allocation) ----
__device__ float g_bufA[Nn * Ff];             // 12.8 MB
__device__ float g_bufB[Nn * Ff];             // 12.8 MB
__device__ float g_S[(size_t)Nn * Cc];        // 25.6 MB (perm2 row layout)
__device__ float g_P[(size_t)Nn * Cc];        // 25.6 MB (perm2 row layout)
__device__ uint32_t g_Ua[3 * 8 * 6 * 4 * 32]; // pre-fragmented tf32 A operands
__device__ float g_dv[3 * Cc];                // folded edge bias (orig col layout)

// ---- f32x2 packed helpers ----
__device__ __forceinline__ ull pack_dup(float x) {
    ull r; asm("mov.b64 %0, {%1, %1};" : "=l"(r) : "f"(x)); return r;
}
__device__ __forceinline__ ull pack2(float x, float y) {
    ull r; asm("mov.b64 %0, {%1, %2};" : "=l"(r) : "f"(x), "f"(y)); return r;
}
__device__ __forceinline__ void fma2(ull& acc, ull a, ull b) {
    asm("fma.rn.f32x2 %0, %1, %2, %0;" : "+l"(acc) : "l"(a), "l"(b));
}

// ---- fast activations (MUFU) ----
__device__ __forceinline__ float ex2_(float x) { float r; asm("ex2.approx.f32 %0, %1;" : "=f"(r) : "f"(x)); return r; }
__device__ __forceinline__ float lg2_(float x) { float r; asm("lg2.approx.f32 %0, %1;" : "=f"(r) : "f"(x)); return r; }
__device__ __forceinline__ float rcp_(float x) { float r; asm("rcp.approx.f32 %0, %1;" : "=f"(r) : "f"(x)); return r; }

__device__ __forceinline__ float sigmoidf_(float x) {
    return rcp_(1.0f + ex2_(-1.4426950408889634f * x));
}
__device__ __forceinline__ float softplusf_(float x) {
    float a = fabsf(x);
    float e = ex2_(-1.4426950408889634f * a);
    return fmaf(lg2_(1.0f + e), 0.6931471805599453f, fmaxf(x, 0.0f));
}

// ---- tf32 helpers ----
__device__ __forceinline__ uint32_t cvt_tf32(float x) {
    uint32_t r; asm("cvt.rna.tf32.f32 %0, %1;" : "=r"(r) : "f"(x)); return r;
}
__device__ __forceinline__ void mma_tf32(float* c,
                                         uint32_t a0, uint32_t a1, uint32_t a2, uint32_t a3,
                                         uint32_t b0, uint32_t b1) {
    asm volatile("mma.sync.aligned.m16n8k8.row.col.f32.tf32.tf32.f32 "
                 "{%0,%1,%2,%3}, {%4,%5,%6,%7}, {%8,%9}, {%0,%1,%2,%3};"
                 : "+f"(c[0]), "+f"(c[1]), "+f"(c[2]), "+f"(c[3])
                 : "r"(a0), "r"(a1), "r"(a2), "r"(a3), "r"(b0), "r"(b1));
}

// ---- cp.async helpers ----
__device__ __forceinline__ void cp4(uint32_t dst, const void* src) {
    asm volatile("cp.async.ca.shared.global [%0], [%1], 4;" :: "r"(dst), "l"(src));
}
__device__ __forceinline__ void cp16(uint32_t dst, const void* src) {
    asm volatile("cp.async.cg.shared.global [%0], [%1], 16;" :: "r"(dst), "l"(src));
}
__device__ __forceinline__ void cp_commit() {
    asm volatile("cp.async.commit_group;");
}
__device__ __forceinline__ void cp_wait_all() {
    asm volatile("cp.async.wait_group 0;");
}

// ---- kernel 1: node0 = node_fea @ Wn + bn ----
__global__ void __launch_bounds__(256) k_node_in(const float* __restrict__ nf,
                                                 const float* __restrict__ Wn,
                                                 const float* __restrict__ bn) {
    __shared__ float s_nf[8 * FN];
    int nbase = blockIdx.x * 8;
    for (int i = threadIdx.x; i < 8 * FN; i += 256)
        s_nf[i] = nf[(size_t)nbase * FN + i];
    __syncthreads();
    int g = threadIdx.x >> 5, c = threadIdx.x & 31;
    ull acc = pack2(bn[2 * c], bn[2 * c + 1]);
    const float* nr = &s_nf[g * FN];
#pragma unroll 4
    for (int k = 0; k < FN; k++) {
        ull w = *(const ull*)&Wn[k * Ff + 2 * c];
        fma2(acc, pack_dup(nr[k]), w);
    }
    *(ull*)&g_bufA[(size_t)(nbase + g) * Ff + 2 * c] = acc;
}

// ---- kernel 2: fold U into pre-arranged tf32 A fragments + dv ----
__global__ void __launch_bounds__(256) k_fold(const float* __restrict__ We,
                                              const float* __restrict__ be,
                                              const float* __restrict__ W1,
                                              const float* __restrict__ W2,
                                              const float* __restrict__ W3) {
    int l = blockIdx.x >> 3, gr = blockIdx.x & 7;
    const float* W = (l == 0) ? W1 : ((l == 1) ? W2 : W3);
    for (int i = threadIdx.x; i < 16 * 48; i += 256) {
        int r = i / 48, k = i - r * 48;
        int c = (r < 8) ? (gr * 8 + r) : (64 + gr * 8 + (r - 8));
        float u = 0.0f;
        if (k < FE) {
#pragma unroll 8
            for (int q = 0; q < Ff; q++)
                u = fmaf(We[k * Ff + q], W[(size_t)(128 + q) * Cc + c], u);
        }
        int kt = k >> 3, kin = k & 7;
        int q = ((r >= 8) ? 1 : 0) + ((kin >= 4) ? 2 : 0);
        int ln = (r & 7) * 4 + (kin & 3);
        g_Ua[(((l * 8 + gr) * 6 + kt) * 4 + q) * 32 + ln] = cvt_tf32(u);
    }
    if (threadIdx.x < 16) {
        int c = gr * 16 + threadIdx.x;
        float dv = 0.0f;
#pragma unroll 8
        for (int q = 0; q < Ff; q++)
            dv = fmaf(be[q], W[(size_t)(128 + q) * Cc + c], dv);
        g_dv[l * Cc + c] = dv;
    }
}

// ---- kernel 3: per-layer S/P precompute (orig-layout math, perm2 store) ----
__global__ void __launch_bounds__(256) k_SP(int srcSel, const float* __restrict__ W,
                                            const float* __restrict__ b, int l) {
    const float* node = srcSel ? g_bufB : g_bufA;
    __shared__ float s_nT[64 * 16];
    int nbase = blockIdx.x * 16;
    for (int i = threadIdx.x; i < 1024; i += 256) {
        int k = i & 63, nl = i >> 6;
        s_nT[k * 16 + nl] = node[(size_t)(nbase + nl) * 64 + k];
    }
    __syncthreads();
    int c = threadIdx.x & 63, gq = threadIdx.x >> 6;
    float2 bv = ((const float2*)b)[c];
    float2 dv = ((const float2*)(g_dv + l * Cc))[c];
    ull s0 = pack2(bv.x + dv.x, bv.y + dv.y);
    ull s1 = s0, s2 = s0, s3 = s0;
    ull p0 = 0, p1 = 0, p2 = 0, p3 = 0;
#pragma unroll 4
    for (int k = 0; k < 64; k++) {
        ull wS = *(const ull*)&W[(size_t)k * Cc + 2 * c];
        ull wP = *(const ull*)&W[(size_t)(64 + k) * Cc + 2 * c];
        float4 nv = *(const float4*)&s_nT[k * 16 + gq * 4];
        ull b0 = pack_dup(nv.x); fma2(s0, b0, wS); fma2(p0, b0, wP);
        ull b1 = pack_dup(nv.y); fma2(s1, b1, wS); fma2(p1, b1, wP);
        ull b2 = pack_dup(nv.z); fma2(s2, b2, wS); fma2(p2, b2, wP);
        ull b3 = pack_dup(nv.w); fma2(s3, b3, wS); fma2(p3, b3, wP);
    }
    int n0 = nbase + gq * 4;
    int pos = (c < 32) ? ((c >> 2) * 16 + ((2 * c) & 7))
                       : (((c - 32) >> 2) * 16 + 8 + ((2 * c) & 7));
    *(ull*)&g_S[(size_t)(n0 + 0) * Cc + pos] = s0;
    *(ull*)&g_S[(size_t)(n0 + 1) * Cc + pos] = s1;
    *(ull*)&g_S[(size_t)(n0 + 2) * Cc + pos] = s2;
    *(ull*)&g_S[(size_t)(n0 + 3) * Cc + pos] = s3;
    *(ull*)&g_P[(size_t)(n0 + 0) * Cc + pos] = p0;
    *(ull*)&g_P[(size_t)(n0 + 1) * Cc + pos] = p1;
    *(ull*)&g_P[(size_t)(n0 + 2) * Cc + pos] = p2;
    *(ull*)&g_P[(size_t)(n0 + 3) * Cc + pos] = p3;
}

// ---- kernel 4: fused conv layer, pipelined transposed tf32 mma ----
__global__ void __launch_bounds__(256, 3) k_conv(int srcSel, int dstSel,
                                                 const float* __restrict__ ef,
                                                 const int* __restrict__ idx,
                                                 const float* __restrict__ alpha_p,
                                                 float* __restrict__ outp, int l) {
    const float* nodein = srcSel ? g_bufB : g_bufA;
    float* dst = (dstSel == 0) ? g_bufA : ((dstSel == 1) ? g_bufB : outp);

    __shared__ __align__(16) float s_ef[2][24 * 52];   // 10 KB double-buffered ef tile
    __shared__ __align__(16) float s_S[16 * Cc];       // 8 KB block's S rows

    const int tid = threadIdx.x;
    const int w = tid >> 5, lane = tid & 31;
    const int lr = lane >> 2, lc = lane & 3;
    const int nbase = blockIdx.x * 16;

    // A fragments (24 coalesced loads, once per block)
    uint32_t Af[6][4];
    const uint32_t* Ua = g_Ua + (size_t)(l * 8 + w) * 6 * 128;
#pragma unroll
    for (int kt = 0; kt < 6; kt++)
#pragma unroll
        for (int q = 0; q < 4; q++)
            Af[kt][q] = Ua[kt * 128 + q * 32 + lane];

    // static zero pads: k = 41..47 of every row, both buffers
    for (int i = tid; i < 2 * 24 * 7; i += 256) {
        int b = i / 168, r = i - b * 168;
        int m = r / 7, k = 41 + (r - m * 7);
        s_ef[b][m * 52 + k] = 0.0f;
    }

    // stage S (coalesced 16B cp.async)
    {
        uint32_t sdst = (uint32_t)__cvta_generic_to_shared(s_S);
        const float* ssrc = g_S + (size_t)nbase * Cc;
        for (int i = tid; i < 512; i += 256)
            cp16(sdst + i * 16, ssrc + i * 4);
    }
    // prefetch ef tile for node 0
    {
        uint32_t d0 = (uint32_t)__cvta_generic_to_shared(&s_ef[0][0]);
        const float* src = ef + (size_t)nbase * 24 * FE;
        for (int t = tid; t < 24 * FE; t += 256) {
            int m = t / FE, k = t - m * FE;
            cp4(d0 + (uint32_t)(m * 52 + k) * 4, src + t);
        }
    }
    cp_commit();

    const float alpha = __ldg(alpha_p);

    for (int ni = 0; ni < 16; ni++) {
        cp_wait_all();
        __syncthreads();

        // prefetch next node's ef tile (overlaps with compute below)
        if (ni < 15) {
            uint32_t dn = (uint32_t)__cvta_generic_to_shared(&s_ef[(ni + 1) & 1][0]);
            const float* src = ef + (size_t)(nbase + ni + 1) * 24 * FE;
            for (int t = tid; t < 24 * FE; t += 256) {
                int m = t / FE, k = t - m * FE;
                cp4(dn + (uint32_t)(m * 52 + k) * 4, src + t);
            }
        }
        cp_commit();

        const float* se = s_ef[ni & 1];
        const int n = nbase + ni;

        // idx + direct P gather into registers (issued before mma chain)
        int ii[6]; float Pf[6], Pc[6];
#pragma unroll
        for (int t = 0; t < 6; t++) {
            int e = (t >> 1) * 8 + 2 * lc + (t & 1);
            ii[t] = __ldg(&idx[n * 24 + e]);
            int iv = (ii[t] < 0) ? 0 : ii[t];
            const float* Pr = g_P + (size_t)iv * Cc + w * 16 + lr;
            Pf[t] = __ldg(Pr);
            Pc[t] = __ldg(Pr + 8);
        }

        // mma: 3 independent chains (B = raw f32 bits, tf32 truncation)
        float c0[4] = {0, 0, 0, 0}, c1[4] = {0, 0, 0, 0}, c2[4] = {0, 0, 0, 0};
#pragma unroll
        for (int kt = 0; kt < 6; kt++) {
            int kb = kt * 8 + lc;
            uint32_t b00 = __float_as_uint(se[(0 * 8 + lr) * 52 + kb]);
            uint32_t b01 = __float_as_uint(se[(0 * 8 + lr) * 52 + kb + 4]);
            uint32_t b10 = __float_as_uint(se[(1 * 8 + lr) * 52 + kb]);
            uint32_t b11 = __float_as_uint(se[(1 * 8 + lr) * 52 + kb + 4]);
            uint32_t b20 = __float_as_uint(se[(2 * 8 + lr) * 52 + kb]);
            uint32_t b21 = __float_as_uint(se[(2 * 8 + lr) * 52 + kb + 4]);
            mma_tf32(c0, Af[kt][0], Af[kt][1], Af[kt][2], Af[kt][3], b00, b01);
            mma_tf32(c1, Af[kt][0], Af[kt][1], Af[kt][2], Af[kt][3], b10, b11);
            mma_tf32(c2, Af[kt][0], Af[kt][1], Af[kt][2], Af[kt][3], b20, b21);
        }

        // epilogue: lane-local (filter, core) pairs
        float Sf = s_S[ni * Cc + w * 16 + lr];
        float Sc = s_S[ni * Cc + w * 16 + 8 + lr];
        float acc = 0.0f;
        if (ii[0] >= 0) acc += sigmoidf_(c0[0] + Sf + Pf[0]) * softplusf_(c0[2] + Sc + Pc[0]);
        if (ii[1] >= 0) acc += sigmoidf_(c0[1] + Sf + Pf[1]) * softplusf_(c0[3] + Sc + Pc[1]);
        if (ii[2] >= 0) acc += sigmoidf_(c1[0] + Sf + Pf[2]) * softplusf_(c1[2] + Sc + Pc[2]);
        if (ii[3] >= 0) acc += sigmoidf_(c1[1] + Sf + Pf[3]) * softplusf_(c1[3] + Sc + Pc[3]);
        if (ii[4] >= 0) acc += sigmoidf_(c2[0] + Sf + Pf[4]) * softplusf_(c2[2] + Sc + Pc[4]);
        if (ii[5] >= 0) acc += sigmoidf_(c2[1] + Sf + Pf[5]) * softplusf_(c2[3] + Sc + Pc[5]);

        acc += __shfl_xor_sync(0xffffffffu, acc, 1);
        acc += __shfl_xor_sync(0xffffffffu, acc, 2);

        if (lc == 0) {
            int j = w * 8 + lr;
            float nin = nodein[(size_t)n * Ff + j];
            dst[(size_t)n * Ff + j] = softplusf_(fmaf(alpha, nin, acc));
        }
    }
}

extern "C" void kernel_launch(void* const* d_in, const int* in_sizes, int n_in,
                              void* d_out, int out_size) {
    const float* nf  = (const float*)d_in[0];
    const float* ef  = (const float*)d_in[1];
    const int*   idx = (const int*)d_in[2];
    const float* Wn  = (const float*)d_in[3];
    const float* bn  = (const float*)d_in[4];
    const float* We  = (const float*)d_in[5];
    const float* be  = (const float*)d_in[6];
    const float* W[3] = {(const float*)d_in[7], (const float*)d_in[10], (const float*)d_in[13]};
    const float* b[3] = {(const float*)d_in[8], (const float*)d_in[11], (const float*)d_in[14]};
    const float* a[3] = {(const float*)d_in[9], (const float*)d_in[12], (const float*)d_in[15]};
    float* out = (float*)d_out;

    k_node_in<<<Nn / 8, 256>>>(nf, Wn, bn);              // -> g_bufA
    k_fold<<<24, 256>>>(We, be, W[0], W[1], W[2]);       // -> g_Ua, g_dv

    // layer 1: A -> B
    k_SP<<<Nn / 16, 256>>>(0, W[0], b[0], 0);
    k_conv<<<Nn / 16, 256>>>(0, 1, ef, idx, a[0], out, 0);
    // layer 2: B -> A
    k_SP<<<Nn / 16, 256>>>(1, W[1], b[1], 1);
    k_conv<<<Nn / 16, 256>>>(1, 0, ef, idx, a[1], out, 1);
    // layer 3: A -> d_out
    k_SP<<<Nn / 16, 256>>>(0, W[2], b[2], 2);
    k_conv<<<Nn / 16, 256>>>(0, 2, ef, idx, a[2], out, 2);
}

// round 6
// speedup vs baseline: 2.6609x; 1.0339x over previous
#include <cuda_runtime.h>
#include <cstdint>

#define Nn 50000
#define Mm 24
#define FN 92
#define FE 41
#define Ff 64
#define Cc 128

typedef unsigned long long ull;

// ---- scratch (static device globals; no allocation) ----
__device__ float g_bufA[Nn * Ff];             // 12.8 MB
__device__ float g_bufB[Nn * Ff];             // 12.8 MB
__device__ float g_S[(size_t)Nn * Cc];        // 25.6 MB (pair layout: [2j]=filter_j, [2j+1]=core_j)
__device__ float g_P[(size_t)Nn * Cc];        // 25.6 MB (pair layout)
__device__ uint32_t g_Ua[3 * 8 * 6 * 4 * 32]; // pre-fragmented tf32 A operands
__device__ float g_dv[3 * Cc];                // folded edge bias (orig col layout)

// ---- f32x2 packed helpers ----
__device__ __forceinline__ ull pack_dup(float x) {
    ull r; asm("mov.b64 %0, {%1, %1};" : "=l"(r) : "f"(x)); return r;
}
__device__ __forceinline__ ull pack2(float x, float y) {
    ull r; asm("mov.b64 %0, {%1, %2};" : "=l"(r) : "f"(x), "f"(y)); return r;
}
__device__ __forceinline__ void unpack2(ull v, float& x, float& y) {
    asm("mov.b64 {%0, %1}, %2;" : "=f"(x), "=f"(y) : "l"(v));
}
__device__ __forceinline__ void fma2(ull& acc, ull a, ull b) {
    asm("fma.rn.f32x2 %0, %1, %2, %0;" : "+l"(acc) : "l"(a), "l"(b));
}

// ---- fast activations (MUFU) ----
__device__ __forceinline__ float ex2_(float x) { float r; asm("ex2.approx.f32 %0, %1;" : "=f"(r) : "f"(x)); return r; }
__device__ __forceinline__ float lg2_(float x) { float r; asm("lg2.approx.f32 %0, %1;" : "=f"(r) : "f"(x)); return r; }
__device__ __forceinline__ float rcp_(float x) { float r; asm("rcp.approx.f32 %0, %1;" : "=f"(r) : "f"(x)); return r; }

__device__ __forceinline__ float sigmoidf_(float x) {
    return rcp_(1.0f + ex2_(-1.4426950408889634f * x));
}
__device__ __forceinline__ float softplusf_(float x) {
    float a = fabsf(x);
    float e = ex2_(-1.4426950408889634f * a);
    return fmaf(lg2_(1.0f + e), 0.6931471805599453f, fmaxf(x, 0.0f));
}

// ---- tf32 helpers ----
__device__ __forceinline__ uint32_t cvt_tf32(float x) {
    uint32_t r; asm("cvt.rna.tf32.f32 %0, %1;" : "=r"(r) : "f"(x)); return r;
}
__device__ __forceinline__ void mma_tf32(float* c,
                                         uint32_t a0, uint32_t a1, uint32_t a2, uint32_t a3,
                                         uint32_t b0, uint32_t b1) {
    asm volatile("mma.sync.aligned.m16n8k8.row.col.f32.tf32.tf32.f32 "
                 "{%0,%1,%2,%3}, {%4,%5,%6,%7}, {%8,%9}, {%0,%1,%2,%3};"
                 : "+f"(c[0]), "+f"(c[1]), "+f"(c[2]), "+f"(c[3])
                 : "r"(a0), "r"(a1), "r"(a2), "r"(a3), "r"(b0), "r"(b1));
}

// ---- cp.async helpers ----
__device__ __forceinline__ void cp4(uint32_t dst, const void* src) {
    asm volatile("cp.async.ca.shared.global [%0], [%1], 4;" :: "r"(dst), "l"(src));
}
__device__ __forceinline__ void cp16(uint32_t dst, const void* src) {
    asm volatile("cp.async.cg.shared.global [%0], [%1], 16;" :: "r"(dst), "l"(src));
}
__device__ __forceinline__ void cp_commit() {
    asm volatile("cp.async.commit_group;");
}
__device__ __forceinline__ void cp_wait_all() {
    asm volatile("cp.async.wait_group 0;");
}

// ---- kernel 1: node0 = node_fea @ Wn + bn ----
__global__ void __launch_bounds__(256) k_node_in(const float* __restrict__ nf,
                                                 const float* __restrict__ Wn,
                                                 const float* __restrict__ bn) {
    __shared__ float s_nf[8 * FN];
    int nbase = blockIdx.x * 8;
    for (int i = threadIdx.x; i < 8 * FN; i += 256)
        s_nf[i] = nf[(size_t)nbase * FN + i];
    __syncthreads();
    int g = threadIdx.x >> 5, c = threadIdx.x & 31;
    ull acc = pack2(bn[2 * c], bn[2 * c + 1]);
    const float* nr = &s_nf[g * FN];
#pragma unroll 4
    for (int k = 0; k < FN; k++) {
        ull w = *(const ull*)&Wn[k * Ff + 2 * c];
        fma2(acc, pack_dup(nr[k]), w);
    }
    *(ull*)&g_bufA[(size_t)(nbase + g) * Ff + 2 * c] = acc;
}

// ---- kernel 2: fold U into pre-arranged tf32 A fragments + dv ----
__global__ void __launch_bounds__(256) k_fold(const float* __restrict__ We,
                                              const float* __restrict__ be,
                                              const float* __restrict__ W1,
                                              const float* __restrict__ W2,
                                              const float* __restrict__ W3) {
    int l = blockIdx.x >> 3, gr = blockIdx.x & 7;
    const float* W = (l == 0) ? W1 : ((l == 1) ? W2 : W3);
    for (int i = threadIdx.x; i < 16 * 48; i += 256) {
        int r = i / 48, k = i - r * 48;
        int c = (r < 8) ? (gr * 8 + r) : (64 + gr * 8 + (r - 8));
        float u = 0.0f;
        if (k < FE) {
#pragma unroll 8
            for (int q = 0; q < Ff; q++)
                u = fmaf(We[k * Ff + q], W[(size_t)(128 + q) * Cc + c], u);
        }
        int kt = k >> 3, kin = k & 7;
        int q = ((r >= 8) ? 1 : 0) + ((kin >= 4) ? 2 : 0);
        int ln = (r & 7) * 4 + (kin & 3);
        g_Ua[(((l * 8 + gr) * 6 + kt) * 4 + q) * 32 + ln] = cvt_tf32(u);
    }
    if (threadIdx.x < 16) {
        int c = gr * 16 + threadIdx.x;
        float dv = 0.0f;
#pragma unroll 8
        for (int q = 0; q < Ff; q++)
            dv = fmaf(be[q], W[(size_t)(128 + q) * Cc + c], dv);
        g_dv[l * Cc + c] = dv;
    }
}

// ---- kernel 3: per-layer S/P precompute (orig-layout math, PAIR-layout store) ----
__global__ void __launch_bounds__(256) k_SP(int srcSel, const float* __restrict__ W,
                                            const float* __restrict__ b, int l) {
    const float* node = srcSel ? g_bufB : g_bufA;
    __shared__ float s_nT[64 * 16];
    int nbase = blockIdx.x * 16;
    for (int i = threadIdx.x; i < 1024; i += 256) {
        int k = i & 63, nl = i >> 6;
        s_nT[k * 16 + nl] = node[(size_t)(nbase + nl) * 64 + k];
    }
    __syncthreads();
    int c = threadIdx.x & 63, gq = threadIdx.x >> 6;
    float2 bv = ((const float2*)b)[c];
    float2 dv = ((const float2*)(g_dv + l * Cc))[c];
    ull s0 = pack2(bv.x + dv.x, bv.y + dv.y);
    ull s1 = s0, s2 = s0, s3 = s0;
    ull p0 = 0, p1 = 0, p2 = 0, p3 = 0;
#pragma unroll 4
    for (int k = 0; k < 64; k++) {
        ull wS = *(const ull*)&W[(size_t)k * Cc + 2 * c];
        ull wP = *(const ull*)&W[(size_t)(64 + k) * Cc + 2 * c];
        float4 nv = *(const float4*)&s_nT[k * 16 + gq * 4];
        ull b0 = pack_dup(nv.x); fma2(s0, b0, wS); fma2(p0, b0, wP);
        ull b1 = pack_dup(nv.y); fma2(s1, b1, wS); fma2(p1, b1, wP);
        ull b2 = pack_dup(nv.z); fma2(s2, b2, wS); fma2(p2, b2, wP);
        ull b3 = pack_dup(nv.w); fma2(s3, b3, wS); fma2(p3, b3, wP);
    }
    int n0 = nbase + gq * 4;
    // pair layout: orig col j<64 (filter) -> pos 2j; j>=64 (core, j=64+jo) -> pos 2jo+1
    // this thread's orig cols are (2c, 2c+1)
    int base = (c < 32) ? (4 * c) : (4 * c - 127);
    float x, y;
    unpack2(s0, x, y); g_S[(size_t)(n0 + 0) * Cc + base] = x; g_S[(size_t)(n0 + 0) * Cc + base + 2] = y;
    unpack2(s1, x, y); g_S[(size_t)(n0 + 1) * Cc + base] = x; g_S[(size_t)(n0 + 1) * Cc + base + 2] = y;
    unpack2(s2, x, y); g_S[(size_t)(n0 + 2) * Cc + base] = x; g_S[(size_t)(n0 + 2) * Cc + base + 2] = y;
    unpack2(s3, x, y); g_S[(size_t)(n0 + 3) * Cc + base] = x; g_S[(size_t)(n0 + 3) * Cc + base + 2] = y;
    unpack2(p0, x, y); g_P[(size_t)(n0 + 0) * Cc + base] = x; g_P[(size_t)(n0 + 0) * Cc + base + 2] = y;
    unpack2(p1, x, y); g_P[(size_t)(n0 + 1) * Cc + base] = x; g_P[(size_t)(n0 + 1) * Cc + base + 2] = y;
    unpack2(p2, x, y); g_P[(size_t)(n0 + 2) * Cc + base] = x; g_P[(size_t)(n0 + 2) * Cc + base + 2] = y;
    unpack2(p3, x, y); g_P[(size_t)(n0 + 3) * Cc + base] = x; g_P[(size_t)(n0 + 3) * Cc + base + 2] = y;
}

// ---- kernel 4: fused conv layer, pipelined transposed tf32 mma ----
__global__ void __launch_bounds__(256, 4) k_conv(int srcSel, int dstSel,
                                                 const float* __restrict__ ef,
                                                 const int* __restrict__ idx,
                                                 const float* __restrict__ alpha_p,
                                                 float* __restrict__ outp, int l) {
    const float* nodein = srcSel ? g_bufB : g_bufA;
    float* dst = (dstSel == 0) ? g_bufA : ((dstSel == 1) ? g_bufB : outp);

    __shared__ __align__(16) float s_ef[2][24 * 52];   // 9.75 KB double-buffered ef tile
    __shared__ __align__(16) int s_idx[16 * 24];       // 1.5 KB all idx for block

    const int tid = threadIdx.x;
    const int w = tid >> 5, lane = tid & 31;
    const int lr = lane >> 2, lc = lane & 3;
    const int nbase = blockIdx.x * 16;

    // A fragments (24 coalesced loads, once per block)
    uint32_t Af[6][4];
    const uint32_t* Ua = g_Ua + (size_t)(l * 8 + w) * 6 * 128;
#pragma unroll
    for (int kt = 0; kt < 6; kt++)
#pragma unroll
        for (int q = 0; q < 4; q++)
            Af[kt][q] = Ua[kt * 128 + q * 32 + lane];

    // static zero pads: k = 41..47 of every row, both buffers
    for (int i = tid; i < 2 * 24 * 7; i += 256) {
        int bq = i / 168, r = i - bq * 168;
        int m = r / 7, k = 41 + (r - m * 7);
        s_ef[bq][m * 52 + k] = 0.0f;
    }

    // precompute this thread's 4 ef-prefetch dest offsets (node-invariant map)
    uint32_t efbase0 = (uint32_t)__cvta_generic_to_shared(&s_ef[0][0]);
    uint32_t efbase1 = (uint32_t)__cvta_generic_to_shared(&s_ef[1][0]);
    uint32_t dq[4];
#pragma unroll
    for (int r = 0; r < 4; r++) {
        int t = tid + r * 256;
        int m = t / FE, k = t - m * FE;
        dq[r] = (uint32_t)(m * 52 + k) * 4;
    }
    const bool has3 = (tid < 24 * FE - 768);

    // stage idx for all 16 nodes (96 cp16)
    if (tid < 96)
        cp16((uint32_t)__cvta_generic_to_shared(s_idx) + tid * 16, idx + (size_t)nbase * 24 + tid * 4);
    // prefetch ef tile for node 0
    {
        const float* src = ef + (size_t)nbase * 24 * FE;
        cp4(efbase0 + dq[0], src + tid);
        cp4(efbase0 + dq[1], src + tid + 256);
        cp4(efbase0 + dq[2], src + tid + 512);
        if (has3) cp4(efbase0 + dq[3], src + tid + 768);
    }
    cp_commit();
    cp_wait_all();
    __syncthreads();

    const float alpha = __ldg(alpha_p);
    const int jo = w * 8 + lr;  // orig feature index owned at lc==0

    for (int ni = 0; ni < 16; ni++) {
        const int n = nbase + ni;

        // ---- early loads: idx (LDS) -> P float2 gathers + S + node-in ----
        unsigned msk = 0;
        float2 Pv[6];
#pragma unroll
        for (int t = 0; t < 6; t++) {
            int e = (t >> 1) * 8 + 2 * lc + (t & 1);
            int ii = s_idx[ni * 24 + e];
            if (ii >= 0) msk |= (1u << t);
            int iv = (ii < 0) ? 0 : ii;
            Pv[t] = *(const float2*)&g_P[(size_t)iv * Cc + 2 * jo];
        }
        float2 Sv = *(const float2*)&g_S[(size_t)n * Cc + 2 * jo];
        float nin = __ldg(&nodein[(size_t)n * Ff + jo]);

        // ---- prefetch next node's ef tile (overlaps with mma + epilogue) ----
        if (ni < 15) {
            uint32_t db = (ni & 1) ? efbase0 : efbase1;
            const float* src = ef + (size_t)(n + 1) * 24 * FE;
            cp4(db + dq[0], src + tid);
            cp4(db + dq[1], src + tid + 256);
            cp4(db + dq[2], src + tid + 512);
            if (has3) cp4(db + dq[3], src + tid + 768);
        }
        cp_commit();

        // ---- mma: 3 independent chains ----
        const float* se = s_ef[ni & 1];
        float c0[4] = {0, 0, 0, 0}, c1[4] = {0, 0, 0, 0}, c2[4] = {0, 0, 0, 0};
#pragma unroll
        for (int kt = 0; kt < 6; kt++) {
            int kb = kt * 8 + lc;
            uint32_t b00 = __float_as_uint(se[(0 * 8 + lr) * 52 + kb]);
            uint32_t b01 = __float_as_uint(se[(0 * 8 + lr) * 52 + kb + 4]);
            uint32_t b10 = __float_as_uint(se[(1 * 8 + lr) * 52 + kb]);
            uint32_t b11 = __float_as_uint(se[(1 * 8 + lr) * 52 + kb + 4]);
            uint32_t b20 = __float_as_uint(se[(2 * 8 + lr) * 52 + kb]);
            uint32_t b21 = __float_as_uint(se[(2 * 8 + lr) * 52 + kb + 4]);
            mma_tf32(c0, Af[kt][0], Af[kt][1], Af[kt][2], Af[kt][3], b00, b01);
            mma_tf32(c1, Af[kt][0], Af[kt][1], Af[kt][2], Af[kt][3], b10, b11);
            mma_tf32(c2, Af[kt][0], Af[kt][1], Af[kt][2], Af[kt][3], b20, b21);
        }

        // ---- epilogue: lane-local (filter, core) pairs ----
        float acc = 0.0f;
        if (msk & 1u)  acc += sigmoidf_(c0[0] + Sv.x + Pv[0].x) * softplusf_(c0[2] + Sv.y + Pv[0].y);
        if (msk & 2u)  acc += sigmoidf_(c0[1] + Sv.x + Pv[1].x) * softplusf_(c0[3] + Sv.y + Pv[1].y);
        if (msk & 4u)  acc += sigmoidf_(c1[0] + Sv.x + Pv[2].x) * softplusf_(c1[2] + Sv.y + Pv[2].y);
        if (msk & 8u)  acc += sigmoidf_(c1[1] + Sv.x + Pv[3].x) * softplusf_(c1[3] + Sv.y + Pv[3].y);
        if (msk & 16u) acc += sigmoidf_(c2[0] + Sv.x + Pv[4].x) * softplusf_(c2[2] + Sv.y + Pv[4].y);
        if (msk & 32u) acc += sigmoidf_(c2[1] + Sv.x + Pv[5].x) * softplusf_(c2[3] + Sv.y + Pv[5].y);

        acc += __shfl_xor_sync(0xffffffffu, acc, 1);
        acc += __shfl_xor_sync(0xffffffffu, acc, 2);

        if (lc == 0)
            dst[(size_t)n * Ff + jo] = softplusf_(fmaf(alpha, nin, acc));

        if (ni < 15) {
            cp_wait_all();
            __syncthreads();
        }
    }
}

extern "C" void kernel_launch(void* const* d_in, const int* in_sizes, int n_in,
                              void* d_out, int out_size) {
    const float* nf  = (const float*)d_in[0];
    const float* ef  = (const float*)d_in[1];
    const int*   idx = (const int*)d_in[2];
    const float* Wn  = (const float*)d_in[3];
    const float* bn  = (const float*)d_in[4];
    const float* We  = (const float*)d_in[5];
    const float* be  = (const float*)d_in[6];
    const float* W[3] = {(const float*)d_in[7], (const float*)d_in[10], (const float*)d_in[13]};
    const float* b[3] = {(const float*)d_in[8], (const float*)d_in[11], (const float*)d_in[14]};
    const float* a[3] = {(const float*)d_in[9], (const float*)d_in[12], (const float*)d_in[15]};
    float* out = (float*)d_out;

    k_node_in<<<Nn / 8, 256>>>(nf, Wn, bn);              // -> g_bufA
    k_fold<<<24, 256>>>(We, be, W[0], W[1], W[2]);       // -> g_Ua, g_dv

    // layer 1: A -> B
    k_SP<<<Nn / 16, 256>>>(0, W[0], b[0], 0);
    k_conv<<<Nn / 16, 256>>>(0, 1, ef, idx, a[0], out, 0);
    // layer 2: B -> A
    k_SP<<<Nn / 16, 256>>>(1, W[1], b[1], 1);
    k_conv<<<Nn / 16, 256>>>(1, 0, ef, idx, a[1], out, 1);
    // layer 3: A -> d_out
    k_SP<<<Nn / 16, 256>>>(0, W[2], b[2], 2);
    k_conv<<<Nn / 16, 256>>>(0, 2, ef, idx, a[2], out, 2);
}

// round 7
// speedup vs baseline: 2.7758x; 1.0432x over previous
#include <cuda_runtime.h>
#include <cstdint>

#define Nn 50000
#define Mm 24
#define FN 92
#define FE 41
#define Ff 64
#define Cc 128

typedef unsigned long long ull;

// ---- scratch (static device globals; no allocation) ----
__device__ float g_bufA[Nn * Ff];             // 12.8 MB
__device__ float g_bufB[Nn * Ff];             // 12.8 MB
__device__ float g_S[(size_t)Nn * Cc];        // 25.6 MB (pair layout: [2j]=filter_j, [2j+1]=core_j)
__device__ float g_P[(size_t)Nn * Cc];        // 25.6 MB (pair layout)
__device__ uint32_t g_Ua[3 * 8 * 6 * 4 * 32]; // pre-fragmented tf32 A operands
__device__ float g_dv[3 * Cc];                // folded edge bias (orig col layout)

// ---- f32x2 packed helpers ----
__device__ __forceinline__ ull pack_dup(float x) {
    ull r; asm("mov.b64 %0, {%1, %1};" : "=l"(r) : "f"(x)); return r;
}
__device__ __forceinline__ ull pack2(float x, float y) {
    ull r; asm("mov.b64 %0, {%1, %2};" : "=l"(r) : "f"(x), "f"(y)); return r;
}
__device__ __forceinline__ void unpack2(ull v, float& x, float& y) {
    asm("mov.b64 {%0, %1}, %2;" : "=f"(x), "=f"(y) : "l"(v));
}
__device__ __forceinline__ void fma2(ull& acc, ull a, ull b) {
    asm("fma.rn.f32x2 %0, %1, %2, %0;" : "+l"(acc) : "l"(a), "l"(b));
}

// ---- fast activations (MUFU) ----
__device__ __forceinline__ float ex2_(float x) { float r; asm("ex2.approx.f32 %0, %1;" : "=f"(r) : "f"(x)); return r; }
__device__ __forceinline__ float lg2_(float x) { float r; asm("lg2.approx.f32 %0, %1;" : "=f"(r) : "f"(x)); return r; }
__device__ __forceinline__ float rcp_(float x) { float r; asm("rcp.approx.f32 %0, %1;" : "=f"(r) : "f"(x)); return r; }

__device__ __forceinline__ float sigmoidf_(float x) {
    return rcp_(1.0f + ex2_(-1.4426950408889634f * x));
}
__device__ __forceinline__ float softplusf_(float x) {
    float a = fabsf(x);
    float e = ex2_(-1.4426950408889634f * a);
    return fmaf(lg2_(1.0f + e), 0.6931471805599453f, fmaxf(x, 0.0f));
}

// ---- tf32 helpers ----
__device__ __forceinline__ uint32_t cvt_tf32(float x) {
    uint32_t r; asm("cvt.rna.tf32.f32 %0, %1;" : "=r"(r) : "f"(x)); return r;
}
__device__ __forceinline__ void mma_tf32(float* c,
                                         uint32_t a0, uint32_t a1, uint32_t a2, uint32_t a3,
                                         uint32_t b0, uint32_t b1) {
    asm volatile("mma.sync.aligned.m16n8k8.row.col.f32.tf32.tf32.f32 "
                 "{%0,%1,%2,%3}, {%4,%5,%6,%7}, {%8,%9}, {%0,%1,%2,%3};"
                 : "+f"(c[0]), "+f"(c[1]), "+f"(c[2]), "+f"(c[3])
                 : "r"(a0), "r"(a1), "r"(a2), "r"(a3), "r"(b0), "r"(b1));
}

// ---- cp.async helpers ----
__device__ __forceinline__ void cp4(uint32_t dst, const void* src) {
    asm volatile("cp.async.ca.shared.global [%0], [%1], 4;" :: "r"(dst), "l"(src));
}
__device__ __forceinline__ void cp16(uint32_t dst, const void* src) {
    asm volatile("cp.async.cg.shared.global [%0], [%1], 16;" :: "r"(dst), "l"(src));
}
__device__ __forceinline__ void cp_commit() {
    asm volatile("cp.async.commit_group;");
}
__device__ __forceinline__ void cp_wait_all() {
    asm volatile("cp.async.wait_group 0;");
}

// ---- kernel 1: node0 = node_fea @ Wn + bn ----
__global__ void __launch_bounds__(256) k_node_in(const float* __restrict__ nf,
                                                 const float* __restrict__ Wn,
                                                 const float* __restrict__ bn) {
    __shared__ float s_nf[8 * FN];
    int nbase = blockIdx.x * 8;
    for (int i = threadIdx.x; i < 8 * FN; i += 256)
        s_nf[i] = nf[(size_t)nbase * FN + i];
    __syncthreads();
    int g = threadIdx.x >> 5, c = threadIdx.x & 31;
    ull acc = pack2(bn[2 * c], bn[2 * c + 1]);
    const float* nr = &s_nf[g * FN];
#pragma unroll 4
    for (int k = 0; k < FN; k++) {
        ull w = *(const ull*)&Wn[k * Ff + 2 * c];
        fma2(acc, pack_dup(nr[k]), w);
    }
    *(ull*)&g_bufA[(size_t)(nbase + g) * Ff + 2 * c] = acc;
}

// ---- kernel 2: fold U into pre-arranged tf32 A fragments + dv ----
__global__ void __launch_bounds__(256) k_fold(const float* __restrict__ We,
                                              const float* __restrict__ be,
                                              const float* __restrict__ W1,
                                              const float* __restrict__ W2,
                                              const float* __restrict__ W3) {
    int l = blockIdx.x >> 3, gr = blockIdx.x & 7;
    const float* W = (l == 0) ? W1 : ((l == 1) ? W2 : W3);
    for (int i = threadIdx.x; i < 16 * 48; i += 256) {
        int r = i / 48, k = i - r * 48;
        int c = (r < 8) ? (gr * 8 + r) : (64 + gr * 8 + (r - 8));
        float u = 0.0f;
        if (k < FE) {
#pragma unroll 8
            for (int q = 0; q < Ff; q++)
                u = fmaf(We[k * Ff + q], W[(size_t)(128 + q) * Cc + c], u);
        }
        int kt = k >> 3, kin = k & 7;
        int q = ((r >= 8) ? 1 : 0) + ((kin >= 4) ? 2 : 0);
        int ln = (r & 7) * 4 + (kin & 3);
        g_Ua[(((l * 8 + gr) * 6 + kt) * 4 + q) * 32 + ln] = cvt_tf32(u);
    }
    if (threadIdx.x < 16) {
        int c = gr * 16 + threadIdx.x;
        float dv = 0.0f;
#pragma unroll 8
        for (int q = 0; q < Ff; q++)
            dv = fmaf(be[q], W[(size_t)(128 + q) * Cc + c], dv);
        g_dv[l * Cc + c] = dv;
    }
}

// ---- kernel 3: per-layer S/P precompute (orig-layout math, PAIR-layout store) ----
__global__ void __launch_bounds__(256) k_SP(int srcSel, const float* __restrict__ W,
                                            const float* __restrict__ b, int l) {
    const float* node = srcSel ? g_bufB : g_bufA;
    __shared__ float s_nT[64 * 16];
    int nbase = blockIdx.x * 16;
    for (int i = threadIdx.x; i < 1024; i += 256) {
        int k = i & 63, nl = i >> 6;
        s_nT[k * 16 + nl] = node[(size_t)(nbase + nl) * 64 + k];
    }
    __syncthreads();
    int c = threadIdx.x & 63, gq = threadIdx.x >> 6;
    float2 bv = ((const float2*)b)[c];
    float2 dv = ((const float2*)(g_dv + l * Cc))[c];
    ull s0 = pack2(bv.x + dv.x, bv.y + dv.y);
    ull s1 = s0, s2 = s0, s3 = s0;
    ull p0 = 0, p1 = 0, p2 = 0, p3 = 0;
#pragma unroll 4
    for (int k = 0; k < 64; k++) {
        ull wS = *(const ull*)&W[(size_t)k * Cc + 2 * c];
        ull wP = *(const ull*)&W[(size_t)(64 + k) * Cc + 2 * c];
        float4 nv = *(const float4*)&s_nT[k * 16 + gq * 4];
        ull b0 = pack_dup(nv.x); fma2(s0, b0, wS); fma2(p0, b0, wP);
        ull b1 = pack_dup(nv.y); fma2(s1, b1, wS); fma2(p1, b1, wP);
        ull b2 = pack_dup(nv.z); fma2(s2, b2, wS); fma2(p2, b2, wP);
        ull b3 = pack_dup(nv.w); fma2(s3, b3, wS); fma2(p3, b3, wP);
    }
    int n0 = nbase + gq * 4;
    int base = (c < 32) ? (4 * c) : (4 * c - 127);
    float x, y;
    unpack2(s0, x, y); g_S[(size_t)(n0 + 0) * Cc + base] = x; g_S[(size_t)(n0 + 0) * Cc + base + 2] = y;
    unpack2(s1, x, y); g_S[(size_t)(n0 + 1) * Cc + base] = x; g_S[(size_t)(n0 + 1) * Cc + base + 2] = y;
    unpack2(s2, x, y); g_S[(size_t)(n0 + 2) * Cc + base] = x; g_S[(size_t)(n0 + 2) * Cc + base + 2] = y;
    unpack2(s3, x, y); g_S[(size_t)(n0 + 3) * Cc + base] = x; g_S[(size_t)(n0 + 3) * Cc + base + 2] = y;
    unpack2(p0, x, y); g_P[(size_t)(n0 + 0) * Cc + base] = x; g_P[(size_t)(n0 + 0) * Cc + base + 2] = y;
    unpack2(p1, x, y); g_P[(size_t)(n0 + 1) * Cc + base] = x; g_P[(size_t)(n0 + 1) * Cc + base + 2] = y;
    unpack2(p2, x, y); g_P[(size_t)(n0 + 2) * Cc + base] = x; g_P[(size_t)(n0 + 2) * Cc + base + 2] = y;
    unpack2(p3, x, y); g_P[(size_t)(n0 + 3) * Cc + base] = x; g_P[(size_t)(n0 + 3) * Cc + base + 2] = y;
}

// ---- kernel 4: fused conv layer, pipelined transposed tf32 mma ----
// ef smem row layout (56-float stride): float offset of orig k =
//   (k & ~7) + (k & 3)*2 + ((k >> 2) & 1)
// so the two B operands (k, k+4) of a thread are one aligned float2.
__global__ void __launch_bounds__(256, 4) k_conv(int srcSel, int dstSel,
                                                 const float* __restrict__ ef,
                                                 const int* __restrict__ idx,
                                                 const float* __restrict__ alpha_p,
                                                 float* __restrict__ outp, int l) {
    const float* nodein = srcSel ? g_bufB : g_bufA;
    float* dst = (dstSel == 0) ? g_bufA : ((dstSel == 1) ? g_bufB : outp);

    __shared__ __align__(16) float s_ef[2][24 * 56];   // 10.5 KB double-buffered ef tile
    __shared__ __align__(16) int s_idx[16 * 24];       // 1.5 KB all idx for block

    const int tid = threadIdx.x;
    const int w = tid >> 5, lane = tid & 31;
    const int lr = lane >> 2, lc = lane & 3;
    const int nbase = blockIdx.x * 16;

    // A fragments (24 coalesced loads, once per block)
    uint32_t Af[6][4];
    const uint32_t* Ua = g_Ua + (size_t)(l * 8 + w) * 6 * 128;
#pragma unroll
    for (int kt = 0; kt < 6; kt++)
#pragma unroll
        for (int q = 0; q < 4; q++)
            Af[kt][q] = Ua[kt * 128 + q * 32 + lane];

    // static zero pads: float offsets 41..47 of every row (mapped image of k=41..47)
    for (int i = tid; i < 2 * 24 * 7; i += 256) {
        int bq = i / 168, r = i - bq * 168;
        int m = r / 7, k = 41 + (r - m * 7);
        s_ef[bq][m * 56 + k] = 0.0f;
    }

    // precompute this thread's 4 ef-prefetch dest offsets (node-invariant map)
    uint32_t efbase0 = (uint32_t)__cvta_generic_to_shared(&s_ef[0][0]);
    uint32_t efbase1 = (uint32_t)__cvta_generic_to_shared(&s_ef[1][0]);
    uint32_t dq[4];
#pragma unroll
    for (int r = 0; r < 4; r++) {
        int t = tid + r * 256;
        int m = t / FE, k = t - m * FE;
        int off = m * 56 + (k & ~7) + (k & 3) * 2 + ((k >> 2) & 1);
        dq[r] = (uint32_t)off * 4;
    }
    const bool has3 = (tid < 24 * FE - 768);

    // stage idx for all 16 nodes (96 cp16)
    if (tid < 96)
        cp16((uint32_t)__cvta_generic_to_shared(s_idx) + tid * 16, idx + (size_t)nbase * 24 + tid * 4);
    // prefetch ef tile for node 0
    {
        const float* src = ef + (size_t)nbase * 24 * FE;
        cp4(efbase0 + dq[0], src + tid);
        cp4(efbase0 + dq[1], src + tid + 256);
        cp4(efbase0 + dq[2], src + tid + 512);
        if (has3) cp4(efbase0 + dq[3], src + tid + 768);
    }
    cp_commit();
    cp_wait_all();
    __syncthreads();

    const float alpha = __ldg(alpha_p);
    const int jo = w * 8 + lr;  // orig feature index owned at lc==0

    for (int ni = 0; ni < 16; ni++) {
        const int n = nbase + ni;

        // ---- early loads: idx (int2 LDS) -> P float2 gathers + S + node-in ----
        int2 ii0 = *(const int2*)&s_idx[ni * 24 + 0 * 8 + 2 * lc];
        int2 ii1 = *(const int2*)&s_idx[ni * 24 + 1 * 8 + 2 * lc];
        int2 ii2 = *(const int2*)&s_idx[ni * 24 + 2 * 8 + 2 * lc];
        int iia[6] = {ii0.x, ii0.y, ii1.x, ii1.y, ii2.x, ii2.y};
        float2 Pv[6];
#pragma unroll
        for (int t = 0; t < 6; t++) {
            int iv = (iia[t] < 0) ? 0 : iia[t];
            Pv[t] = *(const float2*)&g_P[(size_t)iv * Cc + 2 * jo];
        }
        float2 Sv = *(const float2*)&g_S[(size_t)n * Cc + 2 * jo];
        float nin = __ldg(&nodein[(size_t)n * Ff + jo]);

        // ---- prefetch next node's ef tile (overlaps with mma + epilogue) ----
        if (ni < 15) {
            uint32_t db = (ni & 1) ? efbase0 : efbase1;
            const float* src = ef + (size_t)(n + 1) * 24 * FE;
            cp4(db + dq[0], src + tid);
            cp4(db + dq[1], src + tid + 256);
            cp4(db + dq[2], src + tid + 512);
            if (has3) cp4(db + dq[3], src + tid + 768);
        }
        cp_commit();

        // ---- mma: 3 independent chains; B operands via LDS.64 ----
        const float* se = s_ef[ni & 1];
        const float* r0 = se + (0 * 8 + lr) * 56 + 2 * lc;
        const float* r1 = se + (1 * 8 + lr) * 56 + 2 * lc;
        const float* r2 = se + (2 * 8 + lr) * 56 + 2 * lc;
        float c0[4] = {0, 0, 0, 0}, c1[4] = {0, 0, 0, 0}, c2[4] = {0, 0, 0, 0};
#pragma unroll
        for (int kt = 0; kt < 6; kt++) {
            float2 p0 = *(const float2*)(r0 + kt * 8);
            float2 p1 = *(const float2*)(r1 + kt * 8);
            float2 p2 = *(const float2*)(r2 + kt * 8);
            mma_tf32(c0, Af[kt][0], Af[kt][1], Af[kt][2], Af[kt][3],
                     __float_as_uint(p0.x), __float_as_uint(p0.y));
            mma_tf32(c1, Af[kt][0], Af[kt][1], Af[kt][2], Af[kt][3],
                     __float_as_uint(p1.x), __float_as_uint(p1.y));
            mma_tf32(c2, Af[kt][0], Af[kt][1], Af[kt][2], Af[kt][3],
                     __float_as_uint(p2.x), __float_as_uint(p2.y));
        }

        // ---- epilogue: lane-local (filter, core) pairs ----
        float acc = 0.0f;
        if (iia[0] >= 0) acc += sigmoidf_(c0[0] + Sv.x + Pv[0].x) * softplusf_(c0[2] + Sv.y + Pv[0].y);
        if (iia[1] >= 0) acc += sigmoidf_(c0[1] + Sv.x + Pv[1].x) * softplusf_(c0[3] + Sv.y + Pv[1].y);
        if (iia[2] >= 0) acc += sigmoidf_(c1[0] + Sv.x + Pv[2].x) * softplusf_(c1[2] + Sv.y + Pv[2].y);
        if (iia[3] >= 0) acc += sigmoidf_(c1[1] + Sv.x + Pv[3].x) * softplusf_(c1[3] + Sv.y + Pv[3].y);
        if (iia[4] >= 0) acc += sigmoidf_(c2[0] + Sv.x + Pv[4].x) * softplusf_(c2[2] + Sv.y + Pv[4].y);
        if (iia[5] >= 0) acc += sigmoidf_(c2[1] + Sv.x + Pv[5].x) * softplusf_(c2[3] + Sv.y + Pv[5].y);

        acc += __shfl_xor_sync(0xffffffffu, acc, 1);
        acc += __shfl_xor_sync(0xffffffffu, acc, 2);

        if (lc == 0)
            dst[(size_t)n * Ff + jo] = softplusf_(fmaf(alpha, nin, acc));

        if (ni < 15) {
            cp_wait_all();
            __syncthreads();
        }
    }
}

extern "C" void kernel_launch(void* const* d_in, const int* in_sizes, int n_in,
                              void* d_out, int out_size) {
    const float* nf  = (const float*)d_in[0];
    const float* ef  = (const float*)d_in[1];
    const int*   idx = (const int*)d_in[2];
    const float* Wn  = (const float*)d_in[3];
    const float* bn  = (const float*)d_in[4];
    const float* We  = (const float*)d_in[5];
    const float* be  = (const float*)d_in[6];
    const float* W[3] = {(const float*)d_in[7], (const float*)d_in[10], (const float*)d_in[13]};
    const float* b[3] = {(const float*)d_in[8], (const float*)d_in[11], (const float*)d_in[14]};
    const float* a[3] = {(const float*)d_in[9], (const float*)d_in[12], (const float*)d_in[15]};
    float* out = (float*)d_out;

    k_node_in<<<Nn / 8, 256>>>(nf, Wn, bn);              // -> g_bufA
    k_fold<<<24, 256>>>(We, be, W[0], W[1], W[2]);       // -> g_Ua, g_dv

    // layer 1: A -> B
    k_SP<<<Nn / 16, 256>>>(0, W[0], b[0], 0);
    k_conv<<<Nn / 16, 256>>>(0, 1, ef, idx, a[0], out, 0);
    // layer 2: B -> A
    k_SP<<<Nn / 16, 256>>>(1, W[1], b[1], 1);
    k_conv<<<Nn / 16, 256>>>(1, 0, ef, idx, a[1], out, 1);
    // layer 3: A -> d_out
    k_SP<<<Nn / 16, 256>>>(0, W[2], b[2], 2);
    k_conv<<<Nn / 16, 256>>>(0, 2, ef, idx, a[2], out, 2);
}

// round 8
// speedup vs baseline: 3.1529x; 1.1359x over previous
#include <cuda_runtime.h>
#include <cstdint>

#define Nn 50000
#define Mm 24
#define FN 92
#define FE 41
#define Ff 64
#define Cc 128

typedef unsigned long long ull;

// ---- scratch (static device globals; no allocation) ----
__device__ float g_bufA[Nn * Ff];             // 12.8 MB
__device__ float g_bufB[Nn * Ff];             // 12.8 MB
__device__ float g_S[(size_t)Nn * Cc];        // 25.6 MB (pair layout: [2j]=filter_j, [2j+1]=core_j)
__device__ float g_P[(size_t)Nn * Cc];        // 25.6 MB (pair layout)
__device__ uint32_t g_Ua[3 * 8 * 6 * 4 * 32]; // pre-fragmented tf32 A operands
__device__ float g_dv[3 * Cc];                // folded edge bias (orig col layout)

// ---- f32x2 packed helpers ----
__device__ __forceinline__ ull pack_dup(float x) {
    ull r; asm("mov.b64 %0, {%1, %1};" : "=l"(r) : "f"(x)); return r;
}
__device__ __forceinline__ ull pack2(float x, float y) {
    ull r; asm("mov.b64 %0, {%1, %2};" : "=l"(r) : "f"(x), "f"(y)); return r;
}
__device__ __forceinline__ void unpack2(ull v, float& x, float& y) {
    asm("mov.b64 {%0, %1}, %2;" : "=f"(x), "=f"(y) : "l"(v));
}
__device__ __forceinline__ void fma2(ull& acc, ull a, ull b) {
    asm("fma.rn.f32x2 %0, %1, %2, %0;" : "+l"(acc) : "l"(a), "l"(b));
}

// ---- fast activations (MUFU) ----
__device__ __forceinline__ float ex2_(float x) { float r; asm("ex2.approx.f32 %0, %1;" : "=f"(r) : "f"(x)); return r; }
__device__ __forceinline__ float lg2_(float x) { float r; asm("lg2.approx.f32 %0, %1;" : "=f"(r) : "f"(x)); return r; }
__device__ __forceinline__ float rcp_(float x) { float r; asm("rcp.approx.f32 %0, %1;" : "=f"(r) : "f"(x)); return r; }

__device__ __forceinline__ float sigmoidf_(float x) {
    return rcp_(1.0f + ex2_(-1.4426950408889634f * x));
}
__device__ __forceinline__ float softplusf_(float x) {
    float a = fabsf(x);
    float e = ex2_(-1.4426950408889634f * a);
    return fmaf(lg2_(1.0f + e), 0.6931471805599453f, fmaxf(x, 0.0f));
}

// ---- tf32 helpers ----
__device__ __forceinline__ uint32_t cvt_tf32(float x) {
    uint32_t r; asm("cvt.rna.tf32.f32 %0, %1;" : "=r"(r) : "f"(x)); return r;
}
__device__ __forceinline__ void mma_tf32(float* c,
                                         uint32_t a0, uint32_t a1, uint32_t a2, uint32_t a3,
                                         uint32_t b0, uint32_t b1) {
    asm volatile("mma.sync.aligned.m16n8k8.row.col.f32.tf32.tf32.f32 "
                 "{%0,%1,%2,%3}, {%4,%5,%6,%7}, {%8,%9}, {%0,%1,%2,%3};"
                 : "+f"(c[0]), "+f"(c[1]), "+f"(c[2]), "+f"(c[3])
                 : "r"(a0), "r"(a1), "r"(a2), "r"(a3), "r"(b0), "r"(b1));
}

// ---- cp.async helpers ----
__device__ __forceinline__ void cp4(uint32_t dst, const void* src) {
    asm volatile("cp.async.ca.shared.global [%0], [%1], 4;" :: "r"(dst), "l"(src));
}
__device__ __forceinline__ void cp16(uint32_t dst, const void* src) {
    asm volatile("cp.async.cg.shared.global [%0], [%1], 16;" :: "r"(dst), "l"(src));
}
__device__ __forceinline__ void cp_commit() {
    asm volatile("cp.async.commit_group;");
}
__device__ __forceinline__ void cp_wait1() {
    asm volatile("cp.async.wait_group 1;");
}

// ef smem k-map within a row (stride 48): quads (k, k+4, k+8, k+12) contiguous
__device__ __host__ __forceinline__ int ef_off(int k) {
    return ((k >> 4) << 4) + ((k & 3) << 2) + (((k >> 3) & 1) << 1) + ((k >> 2) & 1);
}

// ---- kernel 1: node0 = node_fea @ Wn + bn ----
__global__ void __launch_bounds__(256) k_node_in(const float* __restrict__ nf,
                                                 const float* __restrict__ Wn,
                                                 const float* __restrict__ bn) {
    __shared__ float s_nf[8 * FN];
    int nbase = blockIdx.x * 8;
    for (int i = threadIdx.x; i < 8 * FN; i += 256)
        s_nf[i] = nf[(size_t)nbase * FN + i];
    __syncthreads();
    int g = threadIdx.x >> 5, c = threadIdx.x & 31;
    ull acc = pack2(bn[2 * c], bn[2 * c + 1]);
    const float* nr = &s_nf[g * FN];
#pragma unroll 4
    for (int k = 0; k < FN; k++) {
        ull w = *(const ull*)&Wn[k * Ff + 2 * c];
        fma2(acc, pack_dup(nr[k]), w);
    }
    *(ull*)&g_bufA[(size_t)(nbase + g) * Ff + 2 * c] = acc;
}

// ---- kernel 2: fold U into pre-arranged tf32 A fragments + dv ----
__global__ void __launch_bounds__(256) k_fold(const float* __restrict__ We,
                                              const float* __restrict__ be,
                                              const float* __restrict__ W1,
                                              const float* __restrict__ W2,
                                              const float* __restrict__ W3) {
    int l = blockIdx.x >> 3, gr = blockIdx.x & 7;
    const float* W = (l == 0) ? W1 : ((l == 1) ? W2 : W3);
    for (int i = threadIdx.x; i < 16 * 48; i += 256) {
        int r = i / 48, k = i - r * 48;
        int c = (r < 8) ? (gr * 8 + r) : (64 + gr * 8 + (r - 8));
        float u = 0.0f;
        if (k < FE) {
#pragma unroll 8
            for (int q = 0; q < Ff; q++)
                u = fmaf(We[k * Ff + q], W[(size_t)(128 + q) * Cc + c], u);
        }
        int kt = k >> 3, kin = k & 7;
        int q = ((r >= 8) ? 1 : 0) + ((kin >= 4) ? 2 : 0);
        int ln = (r & 7) * 4 + (kin & 3);
        g_Ua[(((l * 8 + gr) * 6 + kt) * 4 + q) * 32 + ln] = cvt_tf32(u);
    }
    if (threadIdx.x < 16) {
        int c = gr * 16 + threadIdx.x;
        float dv = 0.0f;
#pragma unroll 8
        for (int q = 0; q < Ff; q++)
            dv = fmaf(be[q], W[(size_t)(128 + q) * Cc + c], dv);
        g_dv[l * Cc + c] = dv;
    }
}

// ---- kernel 3: per-layer S/P precompute (orig-layout math, PAIR-layout store) ----
__global__ void __launch_bounds__(256) k_SP(int srcSel, const float* __restrict__ W,
                                            const float* __restrict__ b, int l) {
    const float* node = srcSel ? g_bufB : g_bufA;
    __shared__ float s_nT[64 * 16];
    int nbase = blockIdx.x * 16;
    for (int i = threadIdx.x; i < 1024; i += 256) {
        int k = i & 63, nl = i >> 6;
        s_nT[k * 16 + nl] = node[(size_t)(nbase + nl) * 64 + k];
    }
    __syncthreads();
    int c = threadIdx.x & 63, gq = threadIdx.x >> 6;
    float2 bv = ((const float2*)b)[c];
    float2 dv = ((const float2*)(g_dv + l * Cc))[c];
    ull s0 = pack2(bv.x + dv.x, bv.y + dv.y);
    ull s1 = s0, s2 = s0, s3 = s0;
    ull p0 = 0, p1 = 0, p2 = 0, p3 = 0;
#pragma unroll 4
    for (int k = 0; k < 64; k++) {
        ull wS = *(const ull*)&W[(size_t)k * Cc + 2 * c];
        ull wP = *(const ull*)&W[(size_t)(64 + k) * Cc + 2 * c];
        float4 nv = *(const float4*)&s_nT[k * 16 + gq * 4];
        ull b0 = pack_dup(nv.x); fma2(s0, b0, wS); fma2(p0, b0, wP);
        ull b1 = pack_dup(nv.y); fma2(s1, b1, wS); fma2(p1, b1, wP);
        ull b2 = pack_dup(nv.z); fma2(s2, b2, wS); fma2(p2, b2, wP);
        ull b3 = pack_dup(nv.w); fma2(s3, b3, wS); fma2(p3, b3, wP);
    }
    int n0 = nbase + gq * 4;
    int base = (c < 32) ? (4 * c) : (4 * c - 127);
    float x, y;
    unpack2(s0, x, y); g_S[(size_t)(n0 + 0) * Cc + base] = x; g_S[(size_t)(n0 + 0) * Cc + base + 2] = y;
    unpack2(s1, x, y); g_S[(size_t)(n0 + 1) * Cc + base] = x; g_S[(size_t)(n0 + 1) * Cc + base + 2] = y;
    unpack2(s2, x, y); g_S[(size_t)(n0 + 2) * Cc + base] = x; g_S[(size_t)(n0 + 2) * Cc + base + 2] = y;
    unpack2(s3, x, y); g_S[(size_t)(n0 + 3) * Cc + base] = x; g_S[(size_t)(n0 + 3) * Cc + base + 2] = y;
    unpack2(p0, x, y); g_P[(size_t)(n0 + 0) * Cc + base] = x; g_P[(size_t)(n0 + 0) * Cc + base + 2] = y;
    unpack2(p1, x, y); g_P[(size_t)(n0 + 1) * Cc + base] = x; g_P[(size_t)(n0 + 1) * Cc + base + 2] = y;
    unpack2(p2, x, y); g_P[(size_t)(n0 + 2) * Cc + base] = x; g_P[(size_t)(n0 + 2) * Cc + base + 2] = y;
    unpack2(p3, x, y); g_P[(size_t)(n0 + 3) * Cc + base] = x; g_P[(size_t)(n0 + 3) * Cc + base + 2] = y;
}

// ---- kernel 4: fused conv layer, 2-deep pipelined transposed tf32 mma ----
__global__ void __launch_bounds__(256, 4) k_conv(int srcSel, int dstSel,
                                                 const float* __restrict__ ef,
                                                 const int* __restrict__ idx,
                                                 const float* __restrict__ alpha_p,
                                                 float* __restrict__ outp, int l) {
    const float* nodein = srcSel ? g_bufB : g_bufA;
    float* dst = (dstSel == 0) ? g_bufA : ((dstSel == 1) ? g_bufB : outp);

    __shared__ __align__(16) float s_ef[3][24 * 48];   // 13.5 KB triple-buffered ef tile
    __shared__ __align__(16) int s_idx[16 * 24];       // 1.5 KB all idx for block

    const int tid = threadIdx.x;
    const int w = tid >> 5, lane = tid & 31;
    const int lr = lane >> 2, lc = lane & 3;
    const int nbase = blockIdx.x * 16;

    // A fragments (24 coalesced loads, once per block)
    uint32_t Af[6][4];
    const uint32_t* Ua = g_Ua + (size_t)(l * 8 + w) * 6 * 128;
#pragma unroll
    for (int kt = 0; kt < 6; kt++)
#pragma unroll
        for (int q = 0; q < 4; q++)
            Af[kt][q] = Ua[kt * 128 + q * 32 + lane];

    // static zero pads: image of k=41..47 in every row, all 3 buffers
    for (int i = tid; i < 3 * 24 * 7; i += 256) {
        int bq = i / 168, r = i - bq * 168;
        int m = r / 7, k = 41 + (r - m * 7);
        s_ef[bq][m * 48 + ef_off(k)] = 0.0f;
    }

    // per-thread ef-prefetch dest offsets (node-invariant map)
    uint32_t eb[3];
    eb[0] = (uint32_t)__cvta_generic_to_shared(&s_ef[0][0]);
    eb[1] = (uint32_t)__cvta_generic_to_shared(&s_ef[1][0]);
    eb[2] = (uint32_t)__cvta_generic_to_shared(&s_ef[2][0]);
    uint32_t dq[4];
#pragma unroll
    for (int r = 0; r < 4; r++) {
        int t = tid + r * 256;
        int m = t / FE, k = t - m * FE;
        dq[r] = (uint32_t)(m * 48 + ef_off(k)) * 4;
    }
    const bool has3 = (tid < 24 * FE - 768);

    // prologue: idx staging + prefetch n0 (group 0); prefetch n1 (group 1)
    if (tid < 96)
        cp16((uint32_t)__cvta_generic_to_shared(s_idx) + tid * 16, idx + (size_t)nbase * 24 + tid * 4);
    {
        const float* src = ef + (size_t)nbase * 24 * FE;
        cp4(eb[0] + dq[0], src + tid);
        cp4(eb[0] + dq[1], src + tid + 256);
        cp4(eb[0] + dq[2], src + tid + 512);
        if (has3) cp4(eb[0] + dq[3], src + tid + 768);
        cp_commit();
        src += 24 * FE;
        cp4(eb[1] + dq[0], src + tid);
        cp4(eb[1] + dq[1], src + tid + 256);
        cp4(eb[1] + dq[2], src + tid + 512);
        if (has3) cp4(eb[1] + dq[3], src + tid + 768);
        cp_commit();
    }

    const float alpha = __ldg(alpha_p);
    const int jo = w * 8 + lr;  // orig feature index owned at lc==0
    int bi = 0, pf = 2;

    for (int ni = 0; ni < 16; ni++) {
        const int n = nbase + ni;

        cp_wait1();          // group for node ni complete; ni+1 may be in flight
        __syncthreads();     // also: all warps done with node ni-1's buffer

        // ---- prefetch node ni+2 into the buffer freed by ni-1 ----
        if (ni < 14) {
            uint32_t db = eb[pf];
            const float* src = ef + (size_t)(n + 2) * 24 * FE;
            cp4(db + dq[0], src + tid);
            cp4(db + dq[1], src + tid + 256);
            cp4(db + dq[2], src + tid + 512);
            if (has3) cp4(db + dq[3], src + tid + 768);
        }
        cp_commit();         // commit even when empty to keep group accounting uniform

        // ---- early loads: idx (int2 LDS) -> P float2 gathers + S + node-in ----
        int2 ii0 = *(const int2*)&s_idx[ni * 24 + 0 * 8 + 2 * lc];
        int2 ii1 = *(const int2*)&s_idx[ni * 24 + 1 * 8 + 2 * lc];
        int2 ii2 = *(const int2*)&s_idx[ni * 24 + 2 * 8 + 2 * lc];
        int iia[6] = {ii0.x, ii0.y, ii1.x, ii1.y, ii2.x, ii2.y};
        float2 Pv[6];
#pragma unroll
        for (int t = 0; t < 6; t++) {
            int iv = (iia[t] < 0) ? 0 : iia[t];
            Pv[t] = *(const float2*)&g_P[(size_t)iv * Cc + 2 * jo];
        }
        float2 Sv = *(const float2*)&g_S[(size_t)n * Cc + 2 * jo];
        float nin = __ldg(&nodein[(size_t)n * Ff + jo]);

        // ---- mma: 3 chains; B operands via LDS.128 (two k-steps per load) ----
        const float* se = s_ef[bi];
        const float* r0 = se + (0 * 8 + lr) * 48 + lc * 4;
        const float* r1 = se + (1 * 8 + lr) * 48 + lc * 4;
        const float* r2 = se + (2 * 8 + lr) * 48 + lc * 4;
        float c0[4] = {0, 0, 0, 0}, c1[4] = {0, 0, 0, 0}, c2[4] = {0, 0, 0, 0};
#pragma unroll
        for (int t = 0; t < 3; t++) {
            float4 q0 = *(const float4*)(r0 + t * 16);
            float4 q1 = *(const float4*)(r1 + t * 16);
            float4 q2 = *(const float4*)(r2 + t * 16);
            mma_tf32(c0, Af[2 * t][0], Af[2 * t][1], Af[2 * t][2], Af[2 * t][3],
                     __float_as_uint(q0.x), __float_as_uint(q0.y));
            mma_tf32(c1, Af[2 * t][0], Af[2 * t][1], Af[2 * t][2], Af[2 * t][3],
                     __float_as_uint(q1.x), __float_as_uint(q1.y));
            mma_tf32(c2, Af[2 * t][0], Af[2 * t][1], Af[2 * t][2], Af[2 * t][3],
                     __float_as_uint(q2.x), __float_as_uint(q2.y));
            mma_tf32(c0, Af[2 * t + 1][0], Af[2 * t + 1][1], Af[2 * t + 1][2], Af[2 * t + 1][3],
                     __float_as_uint(q0.z), __float_as_uint(q0.w));
            mma_tf32(c1, Af[2 * t + 1][0], Af[2 * t + 1][1], Af[2 * t + 1][2], Af[2 * t + 1][3],
                     __float_as_uint(q1.z), __float_as_uint(q1.w));
            mma_tf32(c2, Af[2 * t + 1][0], Af[2 * t + 1][1], Af[2 * t + 1][2], Af[2 * t + 1][3],
                     __float_as_uint(q2.z), __float_as_uint(q2.w));
        }

        // ---- epilogue: lane-local (filter, core) pairs ----
        float acc = 0.0f;
        if (iia[0] >= 0) acc += sigmoidf_(c0[0] + Sv.x + Pv[0].x) * softplusf_(c0[2] + Sv.y + Pv[0].y);
        if (iia[1] >= 0) acc += sigmoidf_(c0[1] + Sv.x + Pv[1].x) * softplusf_(c0[3] + Sv.y + Pv[1].y);
        if (iia[2] >= 0) acc += sigmoidf_(c1[0] + Sv.x + Pv[2].x) * softplusf_(c1[2] + Sv.y + Pv[2].y);
        if (iia[3] >= 0) acc += sigmoidf_(c1[1] + Sv.x + Pv[3].x) * softplusf_(c1[3] + Sv.y + Pv[3].y);
        if (iia[4] >= 0) acc += sigmoidf_(c2[0] + Sv.x + Pv[4].x) * softplusf_(c2[2] + Sv.y + Pv[4].y);
        if (iia[5] >= 0) acc += sigmoidf_(c2[1] + Sv.x + Pv[5].x) * softplusf_(c2[3] + Sv.y + Pv[5].y);

        acc += __shfl_xor_sync(0xffffffffu, acc, 1);
        acc += __shfl_xor_sync(0xffffffffu, acc, 2);

        if (lc == 0)
            dst[(size_t)n * Ff + jo] = softplusf_(fmaf(alpha, nin, acc));

        bi = (bi == 2) ? 0 : bi + 1;
        pf = (pf == 2) ? 0 : pf + 1;
    }
}

extern "C" void kernel_launch(void* const* d_in, const int* in_sizes, int n_in,
                              void* d_out, int out_size) {
    const float* nf  = (const float*)d_in[0];
    const float* ef  = (const float*)d_in[1];
    const int*   idx = (const int*)d_in[2];
    const float* Wn  = (const float*)d_in[3];
    const float* bn  = (const float*)d_in[4];
    const float* We  = (const float*)d_in[5];
    const float* be  = (const float*)d_in[6];
    const float* W[3] = {(const float*)d_in[7], (const float*)d_in[10], (const float*)d_in[13]};
    const float* b[3] = {(const float*)d_in[8], (const float*)d_in[11], (const float*)d_in[14]};
    const float* a[3] = {(const float*)d_in[9], (const float*)d_in[12], (const float*)d_in[15]};
    float* out = (float*)d_out;

    k_node_in<<<Nn / 8, 256>>>(nf, Wn, bn);              // -> g_bufA
    k_fold<<<24, 256>>>(We, be, W[0], W[1], W[2]);       // -> g_Ua, g_dv

    // layer 1: A -> B
    k_SP<<<Nn / 16, 256>>>(0, W[0], b[0], 0);
    k_conv<<<Nn / 16, 256>>>(0, 1, ef, idx, a[0], out, 0);
    // layer 2: B -> A
    k_SP<<<Nn / 16, 256>>>(1, W[1], b[1], 1);
    k_conv<<<Nn / 16, 256>>>(1, 0, ef, idx, a[1], out, 1);
    // layer 3: A -> d_out
    k_SP<<<Nn / 16, 256>>>(0, W[2], b[2], 2);
    k_conv<<<Nn / 16, 256>>>(0, 2, ef, idx, a[2], out, 2);
}